// round 1
// baseline (speedup 1.0000x reference)
#include <cuda_runtime.h>
#include <math.h>

// ---------------------------------------------------------------------------
// BarrierNet: x -> MLP (1024 -> 512x2 heads) -> per-row QP (dual PGA, 300 it)
// Dead branches (W23/b23/W33/b33) eliminated: x33 never reaches the output.
// Scratch via __device__ globals (no allocation in kernel_launch).
// ---------------------------------------------------------------------------

#define BMAX 8192

__device__ float g_h1[(size_t)BMAX * 1024];   // relu(x@W1+b1)
__device__ float g_C [(size_t)BMAX * 1024];   // [x21 | x22] (each 512 cols)
__device__ float g_head[(size_t)BMAX * 4];    // p0, p1, 4*sig0, 4*sig1

// ---------------------------------------------------------------------------
// Kernel 1: h1 = relu(x @ W1 + b1)    x:[B,8], W1:[8,1024]
// ---------------------------------------------------------------------------
__global__ void gemm1_kernel(const float* __restrict__ x,
                             const float* __restrict__ W1,
                             const float* __restrict__ b1, int B)
{
    __shared__ float xs[8];
    int row = blockIdx.x;
    if (row >= B) return;
    if (threadIdx.x < 8) xs[threadIdx.x] = x[(size_t)row * 8 + threadIdx.x];
    __syncthreads();
    #pragma unroll
    for (int c = 0; c < 4; ++c) {
        int col = threadIdx.x + c * 256;
        float acc = b1[col];
        #pragma unroll
        for (int k = 0; k < 8; ++k)
            acc = fmaf(xs[k], W1[k * 1024 + col], acc);
        g_h1[(size_t)row * 1024 + col] = fmaxf(acc, 0.0f);
    }
}

// ---------------------------------------------------------------------------
// Kernel 2: C = relu(h1 @ [W21 | W22] + [b21 | b22])
// Classic 128x128x16 fp32 SGEMM, 256 threads, 8x8 microtile, reg prefetch.
// gridDim.x = 8 col-tiles (0-3 -> W21, 4-7 -> W22), gridDim.y = B/128
// ---------------------------------------------------------------------------
__global__ __launch_bounds__(256, 2)
void gemm2_kernel(const float* __restrict__ W21, const float* __restrict__ b21,
                  const float* __restrict__ W22, const float* __restrict__ b22,
                  int B)
{
    __shared__ float As[16][128];
    __shared__ float Bs[16][128];

    const int tid = threadIdx.x;
    const int bx  = blockIdx.x;
    const int by  = blockIdx.y;

    const float* __restrict__ W    = (bx < 4) ? W21 : W22;
    const float* __restrict__ bias = (bx < 4) ? b21 : b22;
    const int nloc = (bx & 3) * 128;   // column offset inside the 512-wide half
    const int m0   = by * 128;

    // A tile loader: 2 x float4 per thread.  idx=tid -> rows 0..63, idx=tid+256 -> +64
    const int aRow = tid >> 2;           // 0..63
    const int aK4  = (tid & 3) * 4;      // 0,4,8,12
    // B tile loader: 2 x float4 per thread over 16(k) x 128(n)
    const int bK   = tid >> 5;           // 0..7 (+8 for second)
    const int bN4  = (tid & 31) * 4;     // 0..124

    const float* __restrict__ Aptr = g_h1 + (size_t)m0 * 1024;
    const float* __restrict__ Wptr = W + nloc;

    float4 aR0, aR1, bR0, bR1;
    aR0 = *(const float4*)(Aptr + (size_t)aRow        * 1024 + aK4);
    aR1 = *(const float4*)(Aptr + (size_t)(aRow + 64) * 1024 + aK4);
    bR0 = *(const float4*)(Wptr + (size_t)bK       * 512 + bN4);
    bR1 = *(const float4*)(Wptr + (size_t)(bK + 8) * 512 + bN4);

    float acc[8][8];
    #pragma unroll
    for (int i = 0; i < 8; ++i)
        #pragma unroll
        for (int j = 0; j < 8; ++j) acc[i][j] = 0.0f;

    const int tx = tid & 15;
    const int ty = tid >> 4;

    for (int t = 0; t < 64; ++t) {
        // commit prefetched tile to smem (A transposed for stride-1 m reads)
        As[aK4 + 0][aRow]      = aR0.x;  As[aK4 + 1][aRow]      = aR0.y;
        As[aK4 + 2][aRow]      = aR0.z;  As[aK4 + 3][aRow]      = aR0.w;
        As[aK4 + 0][aRow + 64] = aR1.x;  As[aK4 + 1][aRow + 64] = aR1.y;
        As[aK4 + 2][aRow + 64] = aR1.z;  As[aK4 + 3][aRow + 64] = aR1.w;
        *(float4*)&Bs[bK][bN4]     = bR0;
        *(float4*)&Bs[bK + 8][bN4] = bR1;
        __syncthreads();

        if (t < 63) {
            const int k0 = (t + 1) * 16;
            aR0 = *(const float4*)(Aptr + (size_t)aRow        * 1024 + k0 + aK4);
            aR1 = *(const float4*)(Aptr + (size_t)(aRow + 64) * 1024 + k0 + aK4);
            bR0 = *(const float4*)(Wptr + (size_t)(k0 + bK)     * 512 + bN4);
            bR1 = *(const float4*)(Wptr + (size_t)(k0 + bK + 8) * 512 + bN4);
        }

        #pragma unroll
        for (int kk = 0; kk < 16; ++kk) {
            float ar[8], br[8];
            float4 v;
            v = *(const float4*)&As[kk][ty * 8];     ar[0]=v.x; ar[1]=v.y; ar[2]=v.z; ar[3]=v.w;
            v = *(const float4*)&As[kk][ty * 8 + 4]; ar[4]=v.x; ar[5]=v.y; ar[6]=v.z; ar[7]=v.w;
            v = *(const float4*)&Bs[kk][tx * 8];     br[0]=v.x; br[1]=v.y; br[2]=v.z; br[3]=v.w;
            v = *(const float4*)&Bs[kk][tx * 8 + 4]; br[4]=v.x; br[5]=v.y; br[6]=v.z; br[7]=v.w;
            #pragma unroll
            for (int i = 0; i < 8; ++i)
                #pragma unroll
                for (int j = 0; j < 8; ++j)
                    acc[i][j] = fmaf(ar[i], br[j], acc[i][j]);
        }
        __syncthreads();
    }

    // epilogue: bias + relu, vectorized store
    #pragma unroll
    for (int i = 0; i < 8; ++i) {
        const int row = m0 + ty * 8 + i;
        const int nb  = nloc + tx * 8;
        float4 o0, o1;
        o0.x = fmaxf(acc[i][0] + bias[nb + 0], 0.0f);
        o0.y = fmaxf(acc[i][1] + bias[nb + 1], 0.0f);
        o0.z = fmaxf(acc[i][2] + bias[nb + 2], 0.0f);
        o0.w = fmaxf(acc[i][3] + bias[nb + 3], 0.0f);
        o1.x = fmaxf(acc[i][4] + bias[nb + 4], 0.0f);
        o1.y = fmaxf(acc[i][5] + bias[nb + 5], 0.0f);
        o1.z = fmaxf(acc[i][6] + bias[nb + 6], 0.0f);
        o1.w = fmaxf(acc[i][7] + bias[nb + 7], 0.0f);
        float* dst = g_C + (size_t)row * 1024 + bx * 128 + tx * 8;
        *(float4*)(dst)     = o0;
        *(float4*)(dst + 4) = o1;
    }
}

// ---------------------------------------------------------------------------
// Kernel 3: heads. One warp per row.
//   p   = x21 @ W31 + b31                 (2 scalars)
//   s32 = 4*sigmoid(x22 @ W32 + b32)      (2 scalars)
// ---------------------------------------------------------------------------
__global__ void heads_kernel(const float* __restrict__ W31, const float* __restrict__ b31,
                             const float* __restrict__ W32, const float* __restrict__ b32,
                             int B)
{
    const int warp = threadIdx.x >> 5;
    const int lane = threadIdx.x & 31;
    const int row  = blockIdx.x * 8 + warp;
    if (row >= B) return;

    const float* __restrict__ c21 = g_C + (size_t)row * 1024;
    const float* __restrict__ c22 = c21 + 512;

    float s0 = 0.f, s1 = 0.f, s2 = 0.f, s3 = 0.f;
    #pragma unroll 4
    for (int k = lane; k < 512; k += 32) {
        const float v1 = c21[k];
        const float v2 = c22[k];
        s0 = fmaf(v1, W31[2 * k],     s0);
        s1 = fmaf(v1, W31[2 * k + 1], s1);
        s2 = fmaf(v2, W32[2 * k],     s2);
        s3 = fmaf(v2, W32[2 * k + 1], s3);
    }
    #pragma unroll
    for (int o = 16; o; o >>= 1) {
        s0 += __shfl_xor_sync(0xffffffffu, s0, o);
        s1 += __shfl_xor_sync(0xffffffffu, s1, o);
        s2 += __shfl_xor_sync(0xffffffffu, s2, o);
        s3 += __shfl_xor_sync(0xffffffffu, s3, o);
    }
    if (lane == 0) {
        g_head[(size_t)row * 4 + 0] = s0 + b31[0];
        g_head[(size_t)row * 4 + 1] = s1 + b31[1];
        g_head[(size_t)row * 4 + 2] = 4.0f / (1.0f + expf(-(s2 + b32[0])));
        g_head[(size_t)row * 4 + 3] = 4.0f / (1.0f + expf(-(s3 + b32[1])));
    }
}

// ---------------------------------------------------------------------------
// Kernel 4: per-row QP.  GGt is rank-2 (G = [g1 g2]), so
//   grad = g1*(g1.lam) + g2*(g2.lam) + q,   ||GGt||_F = sqrt(a^2+2c^2+b^2)
// One thread per row, 300 fixed PGA iterations (nonexpansive map).
// ---------------------------------------------------------------------------
__global__ void qp_kernel(const float* __restrict__ x,
                          const float* __restrict__ mean,
                          const float* __restrict__ stdv,
                          const float* __restrict__ obstacles,
                          float* __restrict__ out, int B)
{
    __shared__ float sObs[24];
    __shared__ float sMean[6], sStd[6];
    const int tid = threadIdx.x;
    if (tid < 24) sObs[tid] = obstacles[tid];
    if (tid < 6) { sMean[tid] = mean[tid]; sStd[tid] = stdv[tid]; }
    __syncthreads();

    const int row = blockIdx.x * blockDim.x + tid;
    if (row >= B) return;

    float x0[6];
    #pragma unroll
    for (int i = 0; i < 6; ++i)
        x0[i] = fmaf(x[(size_t)row * 8 + i], sStd[i], sMean[i]);

    const float px = x0[0], py = x0[1], theta = x0[2], v = x0[3];
    float st, ct;
    sincosf(theta, &st, &ct);

    const float p0  = g_head[(size_t)row * 4 + 0];
    const float p1  = g_head[(size_t)row * 4 + 1];
    const float pp1 = g_head[(size_t)row * 4 + 2];
    const float pp2 = g_head[(size_t)row * 4 + 3];

    const float twovv = 2.0f * v * v;
    const float psum  = pp1 + pp2;
    const float pprod = pp1 * pp2;

    float g1[9], g2[9], q[9];
    #pragma unroll
    for (int m = 0; m < 9; ++m) {
        float ox, oy, orad;
        if (m < 8) { ox = sObs[m * 3]; oy = sObs[m * 3 + 1]; orad = sObs[m * 3 + 2]; }
        else       { ox = x0[4];       oy = x0[5];           orad = 0.5f; }
        const float dx = px - ox, dy = py - oy;
        const float R  = orad + 0.6f;                // 0.5 + orad + 0.1
        const float barrier = dx * dx + dy * dy - R * R;
        const float proj = dx * ct + dy * st;
        const float bdot = 2.0f * v * proj;
        g1[m] = 2.0f * v * (dx * st - dy * ct);      // = -LgLfbu1
        g2[m] = -2.0f * proj;                        // = -LgLfbu2
        const float hm = twovv + psum * bdot + pprod * barrier;
        q[m] = fmaf(g1[m], p0, fmaf(g2[m], p1, hm));
    }

    float a = 0.f, bq = 0.f, c = 0.f;
    #pragma unroll
    for (int m = 0; m < 9; ++m) {
        a  = fmaf(g1[m], g1[m], a);
        bq = fmaf(g2[m], g2[m], bq);
        c  = fmaf(g1[m], g2[m], c);
    }
    const float L = sqrtf(a * a + 2.0f * c * c + bq * bq) + 1e-6f;
    const float alpha = 1.0f / L;

    float lam[9];
    #pragma unroll
    for (int m = 0; m < 9; ++m) lam[m] = 0.0f;

    for (int it = 0; it < 300; ++it) {
        float t1 = 0.f, t2 = 0.f;
        #pragma unroll
        for (int m = 0; m < 9; ++m) {
            t1 = fmaf(g1[m], lam[m], t1);
            t2 = fmaf(g2[m], lam[m], t2);
        }
        #pragma unroll
        for (int m = 0; m < 9; ++m) {
            const float grad = fmaf(g1[m], t1, fmaf(g2[m], t2, q[m]));
            lam[m] = fmaxf(fmaf(-alpha, grad, lam[m]), 0.0f);
        }
    }

    float t1 = 0.f, t2 = 0.f;
    #pragma unroll
    for (int m = 0; m < 9; ++m) {
        t1 = fmaf(g1[m], lam[m], t1);
        t2 = fmaf(g2[m], lam[m], t2);
    }
    out[(size_t)row * 2 + 0] = -p0 - t1;
    out[(size_t)row * 2 + 1] = -p1 - t2;
}

// ---------------------------------------------------------------------------
// Launch. Input order (metadata): x, mean, std, W1, b1, W21, b21, W22, b22,
// W23, b23, W31, b31, W32, b32, W33, b33, obstacles, sgn
// ---------------------------------------------------------------------------
extern "C" void kernel_launch(void* const* d_in, const int* in_sizes, int n_in,
                              void* d_out, int out_size)
{
    const float* x    = (const float*)d_in[0];
    const float* mean = (const float*)d_in[1];
    const float* stdv = (const float*)d_in[2];
    const float* W1   = (const float*)d_in[3];
    const float* b1   = (const float*)d_in[4];
    const float* W21  = (const float*)d_in[5];
    const float* b21  = (const float*)d_in[6];
    const float* W22  = (const float*)d_in[7];
    const float* b22  = (const float*)d_in[8];
    // d_in[9..10]  = W23, b23  (dead)
    const float* W31  = (const float*)d_in[11];
    const float* b31  = (const float*)d_in[12];
    const float* W32  = (const float*)d_in[13];
    const float* b32  = (const float*)d_in[14];
    // d_in[15..16] = W33, b33  (dead)
    const float* obstacles = (const float*)d_in[17];
    // d_in[18] = sgn (unused by reference)
    float* out = (float*)d_out;

    int B = in_sizes[0] / 8;
    if (B > BMAX) B = BMAX;

    gemm1_kernel<<<B, 256>>>(x, W1, b1, B);

    dim3 g2grid(8, (B + 127) / 128);
    gemm2_kernel<<<g2grid, 256>>>(W21, b21, W22, b22, B);

    heads_kernel<<<(B + 7) / 8, 256>>>(W31, b31, W32, b32, B);

    qp_kernel<<<(B + 255) / 256, 256>>>(x, mean, stdv, obstacles, out, B);
}

// round 3
// speedup vs baseline: 2.1228x; 2.1228x over previous
#include <cuda_runtime.h>
#include <cuda_bf16.h>
#include <math.h>
#include <stdint.h>

// ===========================================================================
// BarrierNet on GB300 (sm_103a via generic compute_103 PTX):
//   gemm1 : h1 = relu(x@W1+b1) -> bf16 hi/lo split (g_Ahi/g_Alo), zero heads
//   wconv : [W21|W22]^T -> bf16 hi/lo, n-major (g_Bhi/g_Blo)
//   gemm2 : HMMA (mma.sync bf16) 3-product split GEMM, 128x128 CTA tile,
//           cp.async double-buffer, head dots fused in epilogue (atomicAdd)
//   qp    : per-row rank-2 dual PGA (300 iters)
// C is never materialized. No tcgen05 (harness PTX target is compute_103).
// ===========================================================================

#define BMAX 8192

__device__ __nv_bfloat16 g_Ahi[(size_t)BMAX * 1024];
__device__ __nv_bfloat16 g_Alo[(size_t)BMAX * 1024];
__device__ __nv_bfloat16 g_Bhi[1024 * 1024];   // row n (0..511 W21^T, 512..1023 W22^T), col k
__device__ __nv_bfloat16 g_Blo[1024 * 1024];
__device__ float         g_headAcc[(size_t)BMAX * 4];   // p0,p1 | s2,s3 partials

// ---------------------------------------------------------------------------
// helpers
// ---------------------------------------------------------------------------
__device__ __forceinline__ uint32_t smem_u32(const void* p) {
    uint32_t a;
    asm("{ .reg .u64 t; cvta.to.shared.u64 t, %1; cvt.u32.u64 %0, t; }" : "=r"(a) : "l"(p));
    return a;
}

__device__ __forceinline__ void cpasync16(uint32_t s, const void* g) {
    asm volatile("cp.async.cg.shared.global [%0], [%1], 16;" :: "r"(s), "l"(g));
}
#define CP_COMMIT() asm volatile("cp.async.commit_group;" ::: "memory")
#define CP_WAIT1()  asm volatile("cp.async.wait_group 1;" ::: "memory")

__device__ __forceinline__ void ldsm_x4(uint32_t* r, uint32_t addr) {
    asm volatile("ldmatrix.sync.aligned.m8n8.x4.shared.b16 {%0,%1,%2,%3}, [%4];"
                 : "=r"(r[0]), "=r"(r[1]), "=r"(r[2]), "=r"(r[3]) : "r"(addr));
}

__device__ __forceinline__ void mma_bf16(float* d, const uint32_t* a, const uint32_t* b) {
    asm volatile(
        "mma.sync.aligned.m16n8k16.row.col.f32.bf16.bf16.f32 "
        "{%0,%1,%2,%3}, {%4,%5,%6,%7}, {%8,%9}, {%0,%1,%2,%3};"
        : "+f"(d[0]), "+f"(d[1]), "+f"(d[2]), "+f"(d[3])
        : "r"(a[0]), "r"(a[1]), "r"(a[2]), "r"(a[3]), "r"(b[0]), "r"(b[1]));
}

// ---------------------------------------------------------------------------
// Kernel 1: h1 = relu(x@W1+b1) -> bf16 hi/lo; zero head accumulators
// ---------------------------------------------------------------------------
__global__ void gemm1_kernel(const float* __restrict__ x,
                             const float* __restrict__ W1,
                             const float* __restrict__ b1, int B)
{
    __shared__ float xs[8];
    int row = blockIdx.x;
    if (row >= B) return;
    if (threadIdx.x < 8) xs[threadIdx.x] = x[(size_t)row * 8 + threadIdx.x];
    if (threadIdx.x < 4) g_headAcc[(size_t)row * 4 + threadIdx.x] = 0.0f;
    __syncthreads();
    #pragma unroll
    for (int c = 0; c < 4; ++c) {
        int col = threadIdx.x + c * 256;
        float acc = b1[col];
        #pragma unroll
        for (int k = 0; k < 8; ++k)
            acc = fmaf(xs[k], W1[k * 1024 + col], acc);
        float h = fmaxf(acc, 0.0f);
        __nv_bfloat16 hi = __float2bfloat16(h);
        __nv_bfloat16 lo = __float2bfloat16(h - __bfloat162float(hi));
        g_Ahi[(size_t)row * 1024 + col] = hi;
        g_Alo[(size_t)row * 1024 + col] = lo;
    }
}

// ---------------------------------------------------------------------------
// Kernel 1b: transpose+convert W21/W22 -> g_B{hi,lo}[n][k]
// ---------------------------------------------------------------------------
__global__ void wconv_kernel(const float* __restrict__ W21,
                             const float* __restrict__ W22)
{
    __shared__ float tile[32][33];
    const float* W = blockIdx.z ? W22 : W21;
    const int n0 = blockIdx.x * 32;
    const int k0 = blockIdx.y * 32;
    const int tx = threadIdx.x, ty = threadIdx.y;
    #pragma unroll
    for (int i = ty; i < 32; i += 8)
        tile[i][tx] = W[(size_t)(k0 + i) * 512 + n0 + tx];
    __syncthreads();
    const int zb = blockIdx.z * 512;
    #pragma unroll
    for (int i = ty; i < 32; i += 8) {
        float v = tile[tx][i];                              // W[k0+tx][n0+i]
        __nv_bfloat16 hi = __float2bfloat16(v);
        __nv_bfloat16 lo = __float2bfloat16(v - __bfloat162float(hi));
        size_t o = (size_t)(zb + n0 + i) * 1024 + k0 + tx;
        g_Bhi[o] = hi;
        g_Blo[o] = lo;
    }
}

// ---------------------------------------------------------------------------
// Kernel 2: HMMA split-bf16 GEMM, 128(m) x 128(n) per CTA, K=1024 in 32
// chunks of 32, double-buffered via cp.async. 8 warps = 2(m) x 4(n),
// warp tile 64x32. Per k16: 4x4x3 = 48 mma.m16n8k16.
// Epilogue: bias+relu, head-weight dots, atomicAdd partials. No C written.
// ---------------------------------------------------------------------------
#define PITCHB      80u                   // smem row pitch in bytes (32 bf16 + 8 pad)
#define TILE_BYTES  (128u * PITCHB)       // 10240
#define STAGE_BYTES (4u * TILE_BYTES)     // 40960 (Ahi,Alo,Bhi,Blo)
#define SMEM_DYN    (2u * STAGE_BYTES)    // 81920

__global__ __launch_bounds__(256)
void gemm2_kernel(const float* __restrict__ b21, const float* __restrict__ b22,
                  const float* __restrict__ W31, const float* __restrict__ W32)
{
    extern __shared__ char smem[];
    __shared__ float sBias[128];
    __shared__ float sWh[256];

    const uint32_t sb = smem_u32(smem);
    const int tid  = threadIdx.x;
    const int lane = tid & 31;
    const int wid  = tid >> 5;
    const int wm   = wid & 1;          // 0..1 (m)
    const int wn   = wid >> 1;         // 0..3 (n)
    const int m0   = blockIdx.y * 128;
    const int n0   = blockIdx.x * 128;
    const int half = (n0 >= 512);
    const int nloc = n0 - half * 512;

    if (tid < 128) {
        const float* bp = half ? b22 : b21;
        const float* wp = half ? W32 : W31;
        sBias[tid]       = bp[nloc + tid];
        sWh[2 * tid]     = wp[(nloc + tid) * 2];
        sWh[2 * tid + 1] = wp[(nloc + tid) * 2 + 1];
    }

    const __nv_bfloat16* __restrict__ srcA0 = g_Ahi + (size_t)m0 * 1024;
    const __nv_bfloat16* __restrict__ srcA1 = g_Alo + (size_t)m0 * 1024;
    const __nv_bfloat16* __restrict__ srcB0 = g_Bhi + (size_t)n0 * 1024;
    const __nv_bfloat16* __restrict__ srcB1 = g_Blo + (size_t)n0 * 1024;

    // loader mapping: 2 x 16B per tile per thread
    const int lrow0 = tid >> 2,          lc0 = (tid & 3) * 8;
    const int lrow1 = (tid + 256) >> 2,  lc1 = ((tid + 256) & 3) * 8;

    // ldmatrix per-thread address components
    const uint32_t aRC = (uint32_t)(wm * 64 + (lane & 15)) * PITCHB + (uint32_t)(lane >> 4) * 16u;
    const uint32_t bRC = (uint32_t)(wn * 32 + (lane & 7) + ((lane >> 4) << 3)) * PITCHB
                       + (uint32_t)((lane >> 3) & 1) * 16u;

    float acc[4][4][4];
    #pragma unroll
    for (int mb = 0; mb < 4; ++mb)
        #pragma unroll
        for (int nb = 0; nb < 4; ++nb)
            #pragma unroll
            for (int r = 0; r < 4; ++r) acc[mb][nb][r] = 0.0f;

    // ---- prologue: stage 0 ----
    {
        const uint32_t s = sb;
        cpasync16(s + 0 * TILE_BYTES + lrow0 * PITCHB + lc0 * 2, srcA0 + (size_t)lrow0 * 1024 + lc0);
        cpasync16(s + 0 * TILE_BYTES + lrow1 * PITCHB + lc1 * 2, srcA0 + (size_t)lrow1 * 1024 + lc1);
        cpasync16(s + 1 * TILE_BYTES + lrow0 * PITCHB + lc0 * 2, srcA1 + (size_t)lrow0 * 1024 + lc0);
        cpasync16(s + 1 * TILE_BYTES + lrow1 * PITCHB + lc1 * 2, srcA1 + (size_t)lrow1 * 1024 + lc1);
        cpasync16(s + 2 * TILE_BYTES + lrow0 * PITCHB + lc0 * 2, srcB0 + (size_t)lrow0 * 1024 + lc0);
        cpasync16(s + 2 * TILE_BYTES + lrow1 * PITCHB + lc1 * 2, srcB0 + (size_t)lrow1 * 1024 + lc1);
        cpasync16(s + 3 * TILE_BYTES + lrow0 * PITCHB + lc0 * 2, srcB1 + (size_t)lrow0 * 1024 + lc0);
        cpasync16(s + 3 * TILE_BYTES + lrow1 * PITCHB + lc1 * 2, srcB1 + (size_t)lrow1 * 1024 + lc1);
        CP_COMMIT();
    }

    for (int t = 0; t < 32; ++t) {
        // issue next stage
        if (t + 1 < 32) {
            const uint32_t s = sb + (uint32_t)((t + 1) & 1) * STAGE_BYTES;
            const int k0 = (t + 1) * 32;
            cpasync16(s + 0 * TILE_BYTES + lrow0 * PITCHB + lc0 * 2, srcA0 + (size_t)lrow0 * 1024 + k0 + lc0);
            cpasync16(s + 0 * TILE_BYTES + lrow1 * PITCHB + lc1 * 2, srcA0 + (size_t)lrow1 * 1024 + k0 + lc1);
            cpasync16(s + 1 * TILE_BYTES + lrow0 * PITCHB + lc0 * 2, srcA1 + (size_t)lrow0 * 1024 + k0 + lc0);
            cpasync16(s + 1 * TILE_BYTES + lrow1 * PITCHB + lc1 * 2, srcA1 + (size_t)lrow1 * 1024 + k0 + lc1);
            cpasync16(s + 2 * TILE_BYTES + lrow0 * PITCHB + lc0 * 2, srcB0 + (size_t)lrow0 * 1024 + k0 + lc0);
            cpasync16(s + 2 * TILE_BYTES + lrow1 * PITCHB + lc1 * 2, srcB0 + (size_t)lrow1 * 1024 + k0 + lc1);
            cpasync16(s + 3 * TILE_BYTES + lrow0 * PITCHB + lc0 * 2, srcB1 + (size_t)lrow0 * 1024 + k0 + lc0);
            cpasync16(s + 3 * TILE_BYTES + lrow1 * PITCHB + lc1 * 2, srcB1 + (size_t)lrow1 * 1024 + k0 + lc1);
        }
        CP_COMMIT();
        CP_WAIT1();
        __syncthreads();

        const uint32_t s = sb + (uint32_t)(t & 1) * STAGE_BYTES;
        #pragma unroll
        for (int ks = 0; ks < 2; ++ks) {
            const uint32_t kb = (uint32_t)ks * 32u;
            uint32_t ahi[4][4], alo[4][4];
            #pragma unroll
            for (int mb = 0; mb < 4; ++mb) {
                ldsm_x4(ahi[mb], s + 0 * TILE_BYTES + aRC + (uint32_t)mb * (16u * PITCHB) + kb);
                ldsm_x4(alo[mb], s + 1 * TILE_BYTES + aRC + (uint32_t)mb * (16u * PITCHB) + kb);
            }
            uint32_t bhi[4][2], blo[4][2];
            #pragma unroll
            for (int nbp = 0; nbp < 2; ++nbp) {
                uint32_t r4[4];
                ldsm_x4(r4, s + 2 * TILE_BYTES + bRC + (uint32_t)nbp * (16u * PITCHB) + kb);
                bhi[2 * nbp][0] = r4[0]; bhi[2 * nbp][1] = r4[1];
                bhi[2 * nbp + 1][0] = r4[2]; bhi[2 * nbp + 1][1] = r4[3];
                ldsm_x4(r4, s + 3 * TILE_BYTES + bRC + (uint32_t)nbp * (16u * PITCHB) + kb);
                blo[2 * nbp][0] = r4[0]; blo[2 * nbp][1] = r4[1];
                blo[2 * nbp + 1][0] = r4[2]; blo[2 * nbp + 1][1] = r4[3];
            }
            #pragma unroll
            for (int mb = 0; mb < 4; ++mb)
                #pragma unroll
                for (int nb = 0; nb < 4; ++nb) {
                    mma_bf16(acc[mb][nb], ahi[mb], bhi[nb]);
                    mma_bf16(acc[mb][nb], ahi[mb], blo[nb]);
                    mma_bf16(acc[mb][nb], alo[mb], bhi[nb]);
                }
        }
        __syncthreads();
    }

    // ---- epilogue: bias + relu + head dots, reduce across quad, atomicAdd ----
    const int colBase = wn * 32;
    #pragma unroll
    for (int mb = 0; mb < 4; ++mb) {
        #pragma unroll
        for (int h = 0; h < 2; ++h) {
            float s0 = 0.f, s1 = 0.f;
            #pragma unroll
            for (int nb = 0; nb < 4; ++nb) {
                const int c = colBase + nb * 8 + 2 * (lane & 3);
                const float v0 = fmaxf(acc[mb][nb][h * 2 + 0] + sBias[c],     0.f);
                const float v1 = fmaxf(acc[mb][nb][h * 2 + 1] + sBias[c + 1], 0.f);
                s0 = fmaf(v0, sWh[2 * c],         fmaf(v1, sWh[2 * (c + 1)],     s0));
                s1 = fmaf(v0, sWh[2 * c + 1],     fmaf(v1, sWh[2 * (c + 1) + 1], s1));
            }
            s0 += __shfl_xor_sync(0xffffffffu, s0, 1);
            s0 += __shfl_xor_sync(0xffffffffu, s0, 2);
            s1 += __shfl_xor_sync(0xffffffffu, s1, 1);
            s1 += __shfl_xor_sync(0xffffffffu, s1, 2);
            if ((lane & 3) == 0) {
                const int row = m0 + wm * 64 + mb * 16 + h * 8 + (lane >> 2);
                float* dst = g_headAcc + (size_t)row * 4 + half * 2;
                atomicAdd(dst,     s0);
                atomicAdd(dst + 1, s1);
            }
        }
    }
}

// ---------------------------------------------------------------------------
// Kernel 3: per-row QP (rank-2 dual PGA), 64-thread blocks
// ---------------------------------------------------------------------------
__global__ __launch_bounds__(64)
void qp_kernel(const float* __restrict__ x,
               const float* __restrict__ mean,
               const float* __restrict__ stdv,
               const float* __restrict__ obstacles,
               const float* __restrict__ b31,
               const float* __restrict__ b32,
               float* __restrict__ out, int B)
{
    __shared__ float sObs[24];
    __shared__ float sMean[6], sStd[6], sB[4];
    const int tid = threadIdx.x;
    if (tid < 24) sObs[tid] = obstacles[tid];
    if (tid < 6) { sMean[tid] = mean[tid]; sStd[tid] = stdv[tid]; }
    if (tid < 2) { sB[tid] = b31[tid]; sB[2 + tid] = b32[tid]; }
    __syncthreads();

    const int row = blockIdx.x * 64 + tid;
    if (row >= B) return;

    float x0[6];
    #pragma unroll
    for (int i = 0; i < 6; ++i)
        x0[i] = fmaf(x[(size_t)row * 8 + i], sStd[i], sMean[i]);

    const float px = x0[0], py = x0[1], theta = x0[2], v = x0[3];
    float st, ct;
    sincosf(theta, &st, &ct);

    const float p0  = g_headAcc[(size_t)row * 4 + 0] + sB[0];
    const float p1  = g_headAcc[(size_t)row * 4 + 1] + sB[1];
    const float pp1 = 4.0f / (1.0f + expf(-(g_headAcc[(size_t)row * 4 + 2] + sB[2])));
    const float pp2 = 4.0f / (1.0f + expf(-(g_headAcc[(size_t)row * 4 + 3] + sB[3])));

    const float twovv = 2.0f * v * v;
    const float psum  = pp1 + pp2;
    const float pprod = pp1 * pp2;

    float g1[9], g2[9], q[9];
    #pragma unroll
    for (int m = 0; m < 9; ++m) {
        float ox, oy, orad;
        if (m < 8) { ox = sObs[m * 3]; oy = sObs[m * 3 + 1]; orad = sObs[m * 3 + 2]; }
        else       { ox = x0[4];       oy = x0[5];           orad = 0.5f; }
        const float dx = px - ox, dy = py - oy;
        const float R  = orad + 0.6f;
        const float barrier = dx * dx + dy * dy - R * R;
        const float proj = dx * ct + dy * st;
        const float bdot = 2.0f * v * proj;
        g1[m] = 2.0f * v * (dx * st - dy * ct);
        g2[m] = -2.0f * proj;
        const float hm = twovv + psum * bdot + pprod * barrier;
        q[m] = fmaf(g1[m], p0, fmaf(g2[m], p1, hm));
    }

    float a = 0.f, bq = 0.f, c = 0.f;
    #pragma unroll
    for (int m = 0; m < 9; ++m) {
        a  = fmaf(g1[m], g1[m], a);
        bq = fmaf(g2[m], g2[m], bq);
        c  = fmaf(g1[m], g2[m], c);
    }
    const float L = sqrtf(a * a + 2.0f * c * c + bq * bq) + 1e-6f;
    const float alpha = 1.0f / L;

    float lam[9];
    #pragma unroll
    for (int m = 0; m < 9; ++m) lam[m] = 0.0f;

    for (int it = 0; it < 300; ++it) {
        float t1 = 0.f, t2 = 0.f;
        #pragma unroll
        for (int m = 0; m < 9; ++m) {
            t1 = fmaf(g1[m], lam[m], t1);
            t2 = fmaf(g2[m], lam[m], t2);
        }
        #pragma unroll
        for (int m = 0; m < 9; ++m) {
            const float grad = fmaf(g1[m], t1, fmaf(g2[m], t2, q[m]));
            lam[m] = fmaxf(fmaf(-alpha, grad, lam[m]), 0.0f);
        }
    }

    float t1 = 0.f, t2 = 0.f;
    #pragma unroll
    for (int m = 0; m < 9; ++m) {
        t1 = fmaf(g1[m], lam[m], t1);
        t2 = fmaf(g2[m], lam[m], t2);
    }
    out[(size_t)row * 2 + 0] = -p0 - t1;
    out[(size_t)row * 2 + 1] = -p1 - t2;
}

// ---------------------------------------------------------------------------
// Launch
// ---------------------------------------------------------------------------
extern "C" void kernel_launch(void* const* d_in, const int* in_sizes, int n_in,
                              void* d_out, int out_size)
{
    const float* x    = (const float*)d_in[0];
    const float* mean = (const float*)d_in[1];
    const float* stdv = (const float*)d_in[2];
    const float* W1   = (const float*)d_in[3];
    const float* b1   = (const float*)d_in[4];
    const float* W21  = (const float*)d_in[5];
    const float* b21  = (const float*)d_in[6];
    const float* W22  = (const float*)d_in[7];
    const float* b22  = (const float*)d_in[8];
    const float* W31  = (const float*)d_in[11];
    const float* b31  = (const float*)d_in[12];
    const float* W32  = (const float*)d_in[13];
    const float* b32  = (const float*)d_in[14];
    const float* obstacles = (const float*)d_in[17];
    float* out = (float*)d_out;

    int B = in_sizes[0] / 8;
    if (B > BMAX) B = BMAX;

    static bool attr_set = false;
    if (!attr_set) {
        cudaFuncSetAttribute(gemm2_kernel,
                             cudaFuncAttributeMaxDynamicSharedMemorySize, SMEM_DYN);
        attr_set = true;
    }

    gemm1_kernel<<<B, 256>>>(x, W1, b1, B);
    wconv_kernel<<<dim3(16, 32, 2), dim3(32, 8)>>>(W21, W22);

    dim3 g2(8, (B + 127) / 128);
    gemm2_kernel<<<g2, 256, SMEM_DYN>>>(b21, b22, W31, W32);

    qp_kernel<<<(B + 63) / 64, 64>>>(x, mean, stdv, obstacles, b31, b32, out, B);
}

// round 4
// speedup vs baseline: 2.2265x; 1.0488x over previous
#include <cuda_runtime.h>
#include <cuda_bf16.h>
#include <math.h>
#include <stdint.h>

// ===========================================================================
// BarrierNet on GB300 (generic compute_103 PTX -> HMMA path):
//   gemm1 : h1 = relu(x@W1+b1) -> bf16 hi/lo split; W1 cached in smem
//   wconv : [W21|W22]^T -> bf16 hi/lo, n-major
//   gemm2 : mma.sync bf16 3-product split GEMM, 256x128 CTA tile,
//           cp.async double-buffer, head dots fused in epilogue (atomicAdd)
//   qp    : per-row rank-2 dual PGA, bit-exact fixed-point early exit
// ===========================================================================

#define BMAX 8192

__device__ __align__(16) __nv_bfloat16 g_Ahi[(size_t)BMAX * 1024];
__device__ __align__(16) __nv_bfloat16 g_Alo[(size_t)BMAX * 1024];
__device__ __align__(16) __nv_bfloat16 g_Bhi[1024 * 1024];  // [n][k]
__device__ __align__(16) __nv_bfloat16 g_Blo[1024 * 1024];
__device__ float g_headAcc[(size_t)BMAX * 4];

// ---------------------------------------------------------------------------
__device__ __forceinline__ uint32_t smem_u32(const void* p) {
    uint32_t a;
    asm("{ .reg .u64 t; cvta.to.shared.u64 t, %1; cvt.u32.u64 %0, t; }" : "=r"(a) : "l"(p));
    return a;
}
__device__ __forceinline__ void cpasync16(uint32_t s, const void* g) {
    asm volatile("cp.async.cg.shared.global [%0], [%1], 16;" :: "r"(s), "l"(g));
}
#define CP_COMMIT() asm volatile("cp.async.commit_group;" ::: "memory")
#define CP_WAIT1()  asm volatile("cp.async.wait_group 1;" ::: "memory")

__device__ __forceinline__ void ldsm_x4(uint32_t* r, uint32_t addr) {
    asm volatile("ldmatrix.sync.aligned.m8n8.x4.shared.b16 {%0,%1,%2,%3}, [%4];"
                 : "=r"(r[0]), "=r"(r[1]), "=r"(r[2]), "=r"(r[3]) : "r"(addr));
}
__device__ __forceinline__ void mma_bf16(float* d, const uint32_t* a, const uint32_t* b) {
    asm volatile(
        "mma.sync.aligned.m16n8k16.row.col.f32.bf16.bf16.f32 "
        "{%0,%1,%2,%3}, {%4,%5,%6,%7}, {%8,%9}, {%0,%1,%2,%3};"
        : "+f"(d[0]), "+f"(d[1]), "+f"(d[2]), "+f"(d[3])
        : "r"(a[0]), "r"(a[1]), "r"(a[2]), "r"(a[3]), "r"(b[0]), "r"(b[1]));
}

// ---------------------------------------------------------------------------
// Kernel 1: 32 rows per block, W1 resident in smem.
// ---------------------------------------------------------------------------
__global__ __launch_bounds__(256)
void gemm1_kernel(const float* __restrict__ x,
                  const float* __restrict__ W1,
                  const float* __restrict__ b1, int B)
{
    __shared__ float W1s[8 * 1024];
    __shared__ float xs[32][8];
    const int tid = threadIdx.x;
    const int r0  = blockIdx.x * 32;

    #pragma unroll
    for (int j = 0; j < 32; ++j)
        W1s[tid + j * 256] = W1[tid + j * 256];
    xs[tid >> 3][tid & 7] = x[(size_t)(r0 + (tid >> 3)) * 8 + (tid & 7)];
    if (tid < 128) g_headAcc[(size_t)r0 * 4 + tid] = 0.0f;
    __syncthreads();

    // preload weights for this thread's 4 columns
    float w[4][8];
    float bb[4];
    #pragma unroll
    for (int c = 0; c < 4; ++c) {
        const int col = tid + c * 256;
        bb[c] = b1[col];
        #pragma unroll
        for (int k = 0; k < 8; ++k) w[c][k] = W1s[k * 1024 + col];
    }

    for (int r = 0; r < 32; ++r) {
        float xr[8];
        #pragma unroll
        for (int k = 0; k < 8; ++k) xr[k] = xs[r][k];
        #pragma unroll
        for (int c = 0; c < 4; ++c) {
            float acc = bb[c];
            #pragma unroll
            for (int k = 0; k < 8; ++k) acc = fmaf(xr[k], w[c][k], acc);
            const float h = fmaxf(acc, 0.0f);
            const __nv_bfloat16 hi = __float2bfloat16(h);
            const __nv_bfloat16 lo = __float2bfloat16(h - __bfloat162float(hi));
            const size_t o = (size_t)(r0 + r) * 1024 + tid + c * 256;
            g_Ahi[o] = hi;
            g_Alo[o] = lo;
        }
    }
}

// ---------------------------------------------------------------------------
// Kernel 1b: transpose+convert W21/W22 -> g_B{hi,lo}[n][k]
// ---------------------------------------------------------------------------
__global__ void wconv_kernel(const float* __restrict__ W21,
                             const float* __restrict__ W22)
{
    __shared__ float tile[32][33];
    const float* W = blockIdx.z ? W22 : W21;
    const int n0 = blockIdx.x * 32;
    const int k0 = blockIdx.y * 32;
    const int tx = threadIdx.x, ty = threadIdx.y;
    #pragma unroll
    for (int i = ty; i < 32; i += 8)
        tile[i][tx] = W[(size_t)(k0 + i) * 512 + n0 + tx];
    __syncthreads();
    const int zb = blockIdx.z * 512;
    #pragma unroll
    for (int i = ty; i < 32; i += 8) {
        float v = tile[tx][i];
        __nv_bfloat16 hi = __float2bfloat16(v);
        __nv_bfloat16 lo = __float2bfloat16(v - __bfloat162float(hi));
        size_t o = (size_t)(zb + n0 + i) * 1024 + k0 + tx;
        g_Bhi[o] = hi;
        g_Blo[o] = lo;
    }
}

// ---------------------------------------------------------------------------
// Kernel 2: HMMA split-bf16 GEMM, 256(m) x 128(n) per CTA, K in 32 chunks of
// 32, double-buffered cp.async. 8 warps = 2(m) x 4(n), warp tile 128x32.
// ---------------------------------------------------------------------------
#define PITCHB   80u
#define OFF_A0   0u
#define OFF_A1   (256u * PITCHB)            // 20480
#define OFF_B0   (2u * 256u * PITCHB)       // 40960
#define OFF_B1   (OFF_B0 + 128u * PITCHB)   // 51200
#define STAGE_BYTES (OFF_B1 + 128u * PITCHB) // 61440
#define SMEM_DYN (2u * STAGE_BYTES)          // 122880

__global__ __launch_bounds__(256)
void gemm2_kernel(const float* __restrict__ b21, const float* __restrict__ b22,
                  const float* __restrict__ W31, const float* __restrict__ W32)
{
    extern __shared__ char smem[];
    __shared__ float sBias[128];
    __shared__ float sWh[256];

    const uint32_t sb = smem_u32(smem);
    const int tid  = threadIdx.x;
    const int lane = tid & 31;
    const int wid  = tid >> 5;
    const int wm   = wid & 1;           // 0..1
    const int wn   = wid >> 1;          // 0..3
    const int m0   = blockIdx.y * 256;
    const int n0   = blockIdx.x * 128;
    const int half = (n0 >= 512);
    const int nloc = n0 - half * 512;

    if (tid < 128) {
        const float* bp = half ? b22 : b21;
        const float* wp = half ? W32 : W31;
        sBias[tid]       = bp[nloc + tid];
        sWh[2 * tid]     = wp[(nloc + tid) * 2];
        sWh[2 * tid + 1] = wp[(nloc + tid) * 2 + 1];
    }

    const __nv_bfloat16* __restrict__ srcA0 = g_Ahi + (size_t)m0 * 1024;
    const __nv_bfloat16* __restrict__ srcA1 = g_Alo + (size_t)m0 * 1024;
    const __nv_bfloat16* __restrict__ srcB0 = g_Bhi + (size_t)n0 * 1024;
    const __nv_bfloat16* __restrict__ srcB1 = g_Blo + (size_t)n0 * 1024;

    const int lrow = tid >> 2;           // 0..63
    const int c8   = (tid & 3) * 8;      // element offset
    const uint32_t cB = (uint32_t)(tid & 3) * 16u;

    const uint32_t aRC = (uint32_t)(wm * 128 + (lane & 15)) * PITCHB + (uint32_t)(lane >> 4) * 16u;
    const uint32_t bRC = (uint32_t)(wn * 32 + (lane & 7) + ((lane >> 4) << 3)) * PITCHB
                       + (uint32_t)((lane >> 3) & 1) * 16u;

    float acc[8][4][4];
    #pragma unroll
    for (int mb = 0; mb < 8; ++mb)
        #pragma unroll
        for (int nb = 0; nb < 4; ++nb)
            #pragma unroll
            for (int r = 0; r < 4; ++r) acc[mb][nb][r] = 0.0f;

    // loader: one k32 stage
    #define LOAD_STAGE(sbase, k0)                                                             \
    do {                                                                                      \
        _Pragma("unroll")                                                                     \
        for (int j = 0; j < 4; ++j) {                                                         \
            const int r = lrow + j * 64;                                                      \
            cpasync16((sbase) + OFF_A0 + (uint32_t)r * PITCHB + cB,                           \
                      srcA0 + (size_t)r * 1024 + (k0) + c8);                                  \
            cpasync16((sbase) + OFF_A1 + (uint32_t)r * PITCHB + cB,                           \
                      srcA1 + (size_t)r * 1024 + (k0) + c8);                                  \
        }                                                                                     \
        _Pragma("unroll")                                                                     \
        for (int j = 0; j < 2; ++j) {                                                         \
            const int r = lrow + j * 64;                                                      \
            cpasync16((sbase) + OFF_B0 + (uint32_t)r * PITCHB + cB,                           \
                      srcB0 + (size_t)r * 1024 + (k0) + c8);                                  \
            cpasync16((sbase) + OFF_B1 + (uint32_t)r * PITCHB + cB,                           \
                      srcB1 + (size_t)r * 1024 + (k0) + c8);                                  \
        }                                                                                     \
    } while (0)

    LOAD_STAGE(sb, 0);
    CP_COMMIT();

    for (int t = 0; t < 32; ++t) {
        if (t + 1 < 32) {
            const uint32_t s = sb + (uint32_t)((t + 1) & 1) * STAGE_BYTES;
            LOAD_STAGE(s, (t + 1) * 32);
        }
        CP_COMMIT();
        CP_WAIT1();
        __syncthreads();

        const uint32_t s = sb + (uint32_t)(t & 1) * STAGE_BYTES;
        #pragma unroll
        for (int ks = 0; ks < 2; ++ks) {
            const uint32_t kb = (uint32_t)ks * 32u;
            uint32_t bhi[4][2], blo[4][2];
            #pragma unroll
            for (int nbp = 0; nbp < 2; ++nbp) {
                uint32_t r4[4];
                ldsm_x4(r4, s + OFF_B0 + bRC + (uint32_t)nbp * (16u * PITCHB) + kb);
                bhi[2 * nbp][0] = r4[0]; bhi[2 * nbp][1] = r4[1];
                bhi[2 * nbp + 1][0] = r4[2]; bhi[2 * nbp + 1][1] = r4[3];
                ldsm_x4(r4, s + OFF_B1 + bRC + (uint32_t)nbp * (16u * PITCHB) + kb);
                blo[2 * nbp][0] = r4[0]; blo[2 * nbp][1] = r4[1];
                blo[2 * nbp + 1][0] = r4[2]; blo[2 * nbp + 1][1] = r4[3];
            }
            #pragma unroll
            for (int mb = 0; mb < 8; ++mb) {
                uint32_t ahi[4], alo[4];
                ldsm_x4(ahi, s + OFF_A0 + aRC + (uint32_t)mb * (16u * PITCHB) + kb);
                ldsm_x4(alo, s + OFF_A1 + aRC + (uint32_t)mb * (16u * PITCHB) + kb);
                #pragma unroll
                for (int nb = 0; nb < 4; ++nb) {
                    mma_bf16(acc[mb][nb], ahi, bhi[nb]);
                    mma_bf16(acc[mb][nb], ahi, blo[nb]);
                    mma_bf16(acc[mb][nb], alo, bhi[nb]);
                }
            }
        }
        __syncthreads();
    }

    // epilogue: bias+relu, head dots, quad reduce, atomicAdd
    const int colBase = wn * 32;
    #pragma unroll
    for (int mb = 0; mb < 8; ++mb) {
        #pragma unroll
        for (int h = 0; h < 2; ++h) {
            float s0 = 0.f, s1 = 0.f;
            #pragma unroll
            for (int nb = 0; nb < 4; ++nb) {
                const int c = colBase + nb * 8 + 2 * (lane & 3);
                const float v0 = fmaxf(acc[mb][nb][h * 2 + 0] + sBias[c],     0.f);
                const float v1 = fmaxf(acc[mb][nb][h * 2 + 1] + sBias[c + 1], 0.f);
                s0 = fmaf(v0, sWh[2 * c],     fmaf(v1, sWh[2 * (c + 1)],     s0));
                s1 = fmaf(v0, sWh[2 * c + 1], fmaf(v1, sWh[2 * (c + 1) + 1], s1));
            }
            s0 += __shfl_xor_sync(0xffffffffu, s0, 1);
            s0 += __shfl_xor_sync(0xffffffffu, s0, 2);
            s1 += __shfl_xor_sync(0xffffffffu, s1, 1);
            s1 += __shfl_xor_sync(0xffffffffu, s1, 2);
            if ((lane & 3) == 0) {
                const int row = m0 + wm * 128 + mb * 16 + h * 8 + (lane >> 2);
                float* dst = g_headAcc + (size_t)row * 4 + half * 2;
                atomicAdd(dst,     s0);
                atomicAdd(dst + 1, s1);
            }
        }
    }
}

// ---------------------------------------------------------------------------
// Kernel 3: per-row QP with bit-exact fixed-point early exit.
// ---------------------------------------------------------------------------
__global__ __launch_bounds__(64)
void qp_kernel(const float* __restrict__ x,
               const float* __restrict__ mean,
               const float* __restrict__ stdv,
               const float* __restrict__ obstacles,
               const float* __restrict__ b31,
               const float* __restrict__ b32,
               float* __restrict__ out, int B)
{
    __shared__ float sObs[24];
    __shared__ float sMean[6], sStd[6], sB[4];
    const int tid = threadIdx.x;
    if (tid < 24) sObs[tid] = obstacles[tid];
    if (tid < 6) { sMean[tid] = mean[tid]; sStd[tid] = stdv[tid]; }
    if (tid < 2) { sB[tid] = b31[tid]; sB[2 + tid] = b32[tid]; }
    __syncthreads();

    const int rowReal = blockIdx.x * 64 + tid;
    const int row = rowReal < B ? rowReal : 0;   // keep full warp participating

    float x0[6];
    #pragma unroll
    for (int i = 0; i < 6; ++i)
        x0[i] = fmaf(x[(size_t)row * 8 + i], sStd[i], sMean[i]);

    const float px = x0[0], py = x0[1], theta = x0[2], v = x0[3];
    float st, ct;
    sincosf(theta, &st, &ct);

    const float p0  = g_headAcc[(size_t)row * 4 + 0] + sB[0];
    const float p1  = g_headAcc[(size_t)row * 4 + 1] + sB[1];
    const float pp1 = 4.0f / (1.0f + expf(-(g_headAcc[(size_t)row * 4 + 2] + sB[2])));
    const float pp2 = 4.0f / (1.0f + expf(-(g_headAcc[(size_t)row * 4 + 3] + sB[3])));

    const float twovv = 2.0f * v * v;
    const float psum  = pp1 + pp2;
    const float pprod = pp1 * pp2;

    float g1[9], g2[9], q[9];
    #pragma unroll
    for (int m = 0; m < 9; ++m) {
        float ox, oy, orad;
        if (m < 8) { ox = sObs[m * 3]; oy = sObs[m * 3 + 1]; orad = sObs[m * 3 + 2]; }
        else       { ox = x0[4];       oy = x0[5];           orad = 0.5f; }
        const float dx = px - ox, dy = py - oy;
        const float R  = orad + 0.6f;
        const float barrier = dx * dx + dy * dy - R * R;
        const float proj = dx * ct + dy * st;
        const float bdot = 2.0f * v * proj;
        g1[m] = 2.0f * v * (dx * st - dy * ct);
        g2[m] = -2.0f * proj;
        const float hm = twovv + psum * bdot + pprod * barrier;
        q[m] = fmaf(g1[m], p0, fmaf(g2[m], p1, hm));
    }

    float a = 0.f, bq = 0.f, c = 0.f;
    #pragma unroll
    for (int m = 0; m < 9; ++m) {
        a  = fmaf(g1[m], g1[m], a);
        bq = fmaf(g2[m], g2[m], bq);
        c  = fmaf(g1[m], g2[m], c);
    }
    const float L = sqrtf(a * a + 2.0f * c * c + bq * bq) + 1e-6f;
    const float alpha = 1.0f / L;

    float lam[9];
    #pragma unroll
    for (int m = 0; m < 9; ++m) lam[m] = 0.0f;

    for (int it = 0; it < 300; ++it) {
        // tree-shaped rank-2 reductions (depth 4)
        float t1 = ((g1[0]*lam[0] + g1[1]*lam[1]) + (g1[2]*lam[2] + g1[3]*lam[3]))
                 + ((g1[4]*lam[4] + g1[5]*lam[5]) + (g1[6]*lam[6] + g1[7]*lam[7]))
                 + g1[8]*lam[8];
        float t2 = ((g2[0]*lam[0] + g2[1]*lam[1]) + (g2[2]*lam[2] + g2[3]*lam[3]))
                 + ((g2[4]*lam[4] + g2[5]*lam[5]) + (g2[6]*lam[6] + g2[7]*lam[7]))
                 + g2[8]*lam[8];
        uint32_t ch = 0;
        #pragma unroll
        for (int m = 0; m < 9; ++m) {
            const float grad = fmaf(g1[m], t1, fmaf(g2[m], t2, q[m]));
            const float nl = fmaxf(fmaf(-alpha, grad, lam[m]), 0.0f);
            ch |= (__float_as_uint(nl) ^ __float_as_uint(lam[m]));
            lam[m] = nl;
        }
        // exact fixed point reached by every lane -> remaining iters are no-ops
        if (__all_sync(0xffffffffu, ch == 0)) break;
    }

    float t1 = 0.f, t2 = 0.f;
    #pragma unroll
    for (int m = 0; m < 9; ++m) {
        t1 = fmaf(g1[m], lam[m], t1);
        t2 = fmaf(g2[m], lam[m], t2);
    }
    if (rowReal < B) {
        out[(size_t)rowReal * 2 + 0] = -p0 - t1;
        out[(size_t)rowReal * 2 + 1] = -p1 - t2;
    }
}

// ---------------------------------------------------------------------------
extern "C" void kernel_launch(void* const* d_in, const int* in_sizes, int n_in,
                              void* d_out, int out_size)
{
    const float* x    = (const float*)d_in[0];
    const float* mean = (const float*)d_in[1];
    const float* stdv = (const float*)d_in[2];
    const float* W1   = (const float*)d_in[3];
    const float* b1   = (const float*)d_in[4];
    const float* W21  = (const float*)d_in[5];
    const float* b21  = (const float*)d_in[6];
    const float* W22  = (const float*)d_in[7];
    const float* b22  = (const float*)d_in[8];
    const float* W31  = (const float*)d_in[11];
    const float* b31  = (const float*)d_in[12];
    const float* W32  = (const float*)d_in[13];
    const float* b32  = (const float*)d_in[14];
    const float* obstacles = (const float*)d_in[17];
    float* out = (float*)d_out;

    int B = in_sizes[0] / 8;
    if (B > BMAX) B = BMAX;

    cudaFuncSetAttribute(gemm2_kernel,
                         cudaFuncAttributeMaxDynamicSharedMemorySize, SMEM_DYN);

    gemm1_kernel<<<(B + 31) / 32, 256>>>(x, W1, b1, B);
    wconv_kernel<<<dim3(16, 32, 2), dim3(32, 8)>>>(W21, W22);

    dim3 g2(8, (B + 255) / 256);
    gemm2_kernel<<<g2, 256, SMEM_DYN>>>(b21, b22, W31, W32);

    qp_kernel<<<(B + 63) / 64, 64>>>(x, mean, stdv, obstacles, b31, b32, out, B);
}

// round 5
// speedup vs baseline: 3.1903x; 1.4329x over previous
#include <cuda_runtime.h>
#include <cuda_fp16.h>
#include <math.h>
#include <stdint.h>

// ===========================================================================
// BarrierNet on GB300 (generic compute_103 PTX -> legacy HMMA path, rt~16):
//   gemm1 : h1 = relu(x@W1+b1) -> single fp16 (A)
//   wconv : [W21|W22]^T -> fp16 hi/lo exact split (B carries the precision)
//   gemm2 : mma.sync fp16 2-product GEMM  C = A*Bhi + A*Blo,
//           128x128 CTA tile, 2 CTA/SM, head dots fused in epilogue
//   qp    : per-row rank-2 dual PGA (300 iters, no early exit)
// Error budget: only A's fp16 rounding (~1.4e-4 RMS) -> rel_err ~2e-4.
// ===========================================================================

#define BMAX 8192

__device__ __align__(16) __half g_A  [(size_t)BMAX * 1024];
__device__ __align__(16) __half g_Bhi[1024 * 1024];   // [n][k]
__device__ __align__(16) __half g_Blo[1024 * 1024];
__device__ float g_headAcc[(size_t)BMAX * 4];

// ---------------------------------------------------------------------------
__device__ __forceinline__ uint32_t smem_u32(const void* p) {
    uint32_t a;
    asm("{ .reg .u64 t; cvta.to.shared.u64 t, %1; cvt.u32.u64 %0, t; }" : "=r"(a) : "l"(p));
    return a;
}
__device__ __forceinline__ void cpasync16(uint32_t s, const void* g) {
    asm volatile("cp.async.cg.shared.global [%0], [%1], 16;" :: "r"(s), "l"(g));
}
#define CP_COMMIT() asm volatile("cp.async.commit_group;" ::: "memory")
#define CP_WAIT1()  asm volatile("cp.async.wait_group 1;" ::: "memory")

__device__ __forceinline__ void ldsm_x4(uint32_t* r, uint32_t addr) {
    asm volatile("ldmatrix.sync.aligned.m8n8.x4.shared.b16 {%0,%1,%2,%3}, [%4];"
                 : "=r"(r[0]), "=r"(r[1]), "=r"(r[2]), "=r"(r[3]) : "r"(addr));
}
__device__ __forceinline__ void mma_f16(float* d, const uint32_t* a, const uint32_t* b) {
    asm volatile(
        "mma.sync.aligned.m16n8k16.row.col.f32.f16.f16.f32 "
        "{%0,%1,%2,%3}, {%4,%5,%6,%7}, {%8,%9}, {%0,%1,%2,%3};"
        : "+f"(d[0]), "+f"(d[1]), "+f"(d[2]), "+f"(d[3])
        : "r"(a[0]), "r"(a[1]), "r"(a[2]), "r"(a[3]), "r"(b[0]), "r"(b[1]));
}

// ---------------------------------------------------------------------------
// Kernel 1: 32 rows per block, W1 resident in smem -> fp16 A
// ---------------------------------------------------------------------------
__global__ __launch_bounds__(256)
void gemm1_kernel(const float* __restrict__ x,
                  const float* __restrict__ W1,
                  const float* __restrict__ b1, int B)
{
    __shared__ float W1s[8 * 1024];
    __shared__ float xs[32][8];
    const int tid = threadIdx.x;
    const int r0  = blockIdx.x * 32;

    #pragma unroll
    for (int j = 0; j < 32; ++j)
        W1s[tid + j * 256] = W1[tid + j * 256];
    xs[tid >> 3][tid & 7] = x[(size_t)(r0 + (tid >> 3)) * 8 + (tid & 7)];
    if (tid < 128) g_headAcc[(size_t)r0 * 4 + tid] = 0.0f;
    __syncthreads();

    float w[4][8], bb[4];
    #pragma unroll
    for (int c = 0; c < 4; ++c) {
        const int col = tid + c * 256;
        bb[c] = b1[col];
        #pragma unroll
        for (int k = 0; k < 8; ++k) w[c][k] = W1s[k * 1024 + col];
    }

    for (int r = 0; r < 32; ++r) {
        float xr[8];
        #pragma unroll
        for (int k = 0; k < 8; ++k) xr[k] = xs[r][k];
        #pragma unroll
        for (int c = 0; c < 4; ++c) {
            float acc = bb[c];
            #pragma unroll
            for (int k = 0; k < 8; ++k) acc = fmaf(xr[k], w[c][k], acc);
            g_A[(size_t)(r0 + r) * 1024 + tid + c * 256] =
                __float2half(fmaxf(acc, 0.0f));
        }
    }
}

// ---------------------------------------------------------------------------
// Kernel 1b: transpose + exact fp16 hi/lo split of W21/W22 -> g_B{hi,lo}[n][k]
// ---------------------------------------------------------------------------
__global__ void wconv_kernel(const float* __restrict__ W21,
                             const float* __restrict__ W22)
{
    __shared__ float tile[32][33];
    const float* W = blockIdx.z ? W22 : W21;
    const int n0 = blockIdx.x * 32;
    const int k0 = blockIdx.y * 32;
    const int tx = threadIdx.x, ty = threadIdx.y;
    #pragma unroll
    for (int i = ty; i < 32; i += 8)
        tile[i][tx] = W[(size_t)(k0 + i) * 512 + n0 + tx];
    __syncthreads();
    const int zb = blockIdx.z * 512;
    #pragma unroll
    for (int i = ty; i < 32; i += 8) {
        float v = tile[tx][i];
        __half hi = __float2half(v);
        __half lo = __float2half(v - __half2float(hi));
        size_t o = (size_t)(zb + n0 + i) * 1024 + k0 + tx;
        g_Bhi[o] = hi;
        g_Blo[o] = lo;
    }
}

// ---------------------------------------------------------------------------
// Kernel 2: fp16 2-product GEMM, 128(m) x 128(n) CTA tile, 2 CTA/SM.
// 8 warps = 2(m) x 4(n), warp tile 64x32. Per k16: 4mb x 4nb x 2 = 32 mma.
// ---------------------------------------------------------------------------
#define PITCHB   80u
#define OFF_A    0u
#define OFF_B0   (128u * PITCHB)            // 10240
#define OFF_B1   (2u * 128u * PITCHB)       // 20480
#define STAGE_BYTES (3u * 128u * PITCHB)    // 30720
#define SMEM_DYN (2u * STAGE_BYTES)         // 61440

__global__ __launch_bounds__(256, 2)
void gemm2_kernel(const float* __restrict__ b21, const float* __restrict__ b22,
                  const float* __restrict__ W31, const float* __restrict__ W32)
{
    extern __shared__ char smem[];
    __shared__ float sBias[128];
    __shared__ float sWh[256];

    const uint32_t sb = smem_u32(smem);
    const int tid  = threadIdx.x;
    const int lane = tid & 31;
    const int wid  = tid >> 5;
    const int wm   = wid & 1;           // 0..1
    const int wn   = wid >> 1;          // 0..3
    const int m0   = blockIdx.y * 128;
    const int n0   = blockIdx.x * 128;
    const int half = (n0 >= 512);
    const int nloc = n0 - half * 512;

    if (tid < 128) {
        const float* bp = half ? b22 : b21;
        const float* wp = half ? W32 : W31;
        sBias[tid]       = bp[nloc + tid];
        sWh[2 * tid]     = wp[(nloc + tid) * 2];
        sWh[2 * tid + 1] = wp[(nloc + tid) * 2 + 1];
    }

    const __half* __restrict__ srcA  = g_A   + (size_t)m0 * 1024;
    const __half* __restrict__ srcB0 = g_Bhi + (size_t)n0 * 1024;
    const __half* __restrict__ srcB1 = g_Blo + (size_t)n0 * 1024;

    const int lrow = tid >> 2;           // 0..63
    const int c8   = (tid & 3) * 8;
    const uint32_t cB = (uint32_t)(tid & 3) * 16u;

    const uint32_t aRC = (uint32_t)(wm * 64 + (lane & 15)) * PITCHB + (uint32_t)(lane >> 4) * 16u;
    const uint32_t bRC = (uint32_t)(wn * 32 + (lane & 7) + ((lane >> 4) << 3)) * PITCHB
                       + (uint32_t)((lane >> 3) & 1) * 16u;

    float acc[4][4][4];
    #pragma unroll
    for (int mb = 0; mb < 4; ++mb)
        #pragma unroll
        for (int nb = 0; nb < 4; ++nb)
            #pragma unroll
            for (int r = 0; r < 4; ++r) acc[mb][nb][r] = 0.0f;

    #define LOAD_STAGE(sbase, k0)                                                   \
    do {                                                                            \
        _Pragma("unroll")                                                           \
        for (int j = 0; j < 2; ++j) {                                               \
            const int r = lrow + j * 64;                                            \
            cpasync16((sbase) + OFF_A  + (uint32_t)r * PITCHB + cB,                 \
                      srcA  + (size_t)r * 1024 + (k0) + c8);                        \
            cpasync16((sbase) + OFF_B0 + (uint32_t)r * PITCHB + cB,                 \
                      srcB0 + (size_t)r * 1024 + (k0) + c8);                        \
            cpasync16((sbase) + OFF_B1 + (uint32_t)r * PITCHB + cB,                 \
                      srcB1 + (size_t)r * 1024 + (k0) + c8);                        \
        }                                                                           \
    } while (0)

    LOAD_STAGE(sb, 0);
    CP_COMMIT();

    for (int t = 0; t < 32; ++t) {
        if (t + 1 < 32) {
            const uint32_t s = sb + (uint32_t)((t + 1) & 1) * STAGE_BYTES;
            LOAD_STAGE(s, (t + 1) * 32);
        }
        CP_COMMIT();
        CP_WAIT1();
        __syncthreads();

        const uint32_t s = sb + (uint32_t)(t & 1) * STAGE_BYTES;
        #pragma unroll
        for (int ks = 0; ks < 2; ++ks) {
            const uint32_t kb = (uint32_t)ks * 32u;
            uint32_t bhi[4][2], blo[4][2];
            #pragma unroll
            for (int nbp = 0; nbp < 2; ++nbp) {
                uint32_t r4[4];
                ldsm_x4(r4, s + OFF_B0 + bRC + (uint32_t)nbp * (16u * PITCHB) + kb);
                bhi[2 * nbp][0] = r4[0]; bhi[2 * nbp][1] = r4[1];
                bhi[2 * nbp + 1][0] = r4[2]; bhi[2 * nbp + 1][1] = r4[3];
                ldsm_x4(r4, s + OFF_B1 + bRC + (uint32_t)nbp * (16u * PITCHB) + kb);
                blo[2 * nbp][0] = r4[0]; blo[2 * nbp][1] = r4[1];
                blo[2 * nbp + 1][0] = r4[2]; blo[2 * nbp + 1][1] = r4[3];
            }
            #pragma unroll
            for (int mb = 0; mb < 4; ++mb) {
                uint32_t a4[4];
                ldsm_x4(a4, s + OFF_A + aRC + (uint32_t)mb * (16u * PITCHB) + kb);
                #pragma unroll
                for (int nb = 0; nb < 4; ++nb) {
                    mma_f16(acc[mb][nb], a4, bhi[nb]);
                    mma_f16(acc[mb][nb], a4, blo[nb]);
                }
            }
        }
        __syncthreads();
    }

    // epilogue: bias+relu, head dots, quad reduce, atomicAdd
    const int colBase = wn * 32;
    #pragma unroll
    for (int mb = 0; mb < 4; ++mb) {
        #pragma unroll
        for (int h = 0; h < 2; ++h) {
            float s0 = 0.f, s1 = 0.f;
            #pragma unroll
            for (int nb = 0; nb < 4; ++nb) {
                const int c = colBase + nb * 8 + 2 * (lane & 3);
                const float v0 = fmaxf(acc[mb][nb][h * 2 + 0] + sBias[c],     0.f);
                const float v1 = fmaxf(acc[mb][nb][h * 2 + 1] + sBias[c + 1], 0.f);
                s0 = fmaf(v0, sWh[2 * c],     fmaf(v1, sWh[2 * (c + 1)],     s0));
                s1 = fmaf(v0, sWh[2 * c + 1], fmaf(v1, sWh[2 * (c + 1) + 1], s1));
            }
            s0 += __shfl_xor_sync(0xffffffffu, s0, 1);
            s0 += __shfl_xor_sync(0xffffffffu, s0, 2);
            s1 += __shfl_xor_sync(0xffffffffu, s1, 1);
            s1 += __shfl_xor_sync(0xffffffffu, s1, 2);
            if ((lane & 3) == 0) {
                const int row = m0 + wm * 64 + mb * 16 + h * 8 + (lane >> 2);
                float* dst = g_headAcc + (size_t)row * 4 + half * 2;
                atomicAdd(dst,     s0);
                atomicAdd(dst + 1, s1);
            }
        }
    }
}

// ---------------------------------------------------------------------------
// Kernel 3: per-row QP (rank-2 dual PGA, fixed 300 iters — no early exit)
// ---------------------------------------------------------------------------
__global__ __launch_bounds__(64)
void qp_kernel(const float* __restrict__ x,
               const float* __restrict__ mean,
               const float* __restrict__ stdv,
               const float* __restrict__ obstacles,
               const float* __restrict__ b31,
               const float* __restrict__ b32,
               float* __restrict__ out, int B)
{
    __shared__ float sObs[24];
    __shared__ float sMean[6], sStd[6], sB[4];
    const int tid = threadIdx.x;
    if (tid < 24) sObs[tid] = obstacles[tid];
    if (tid < 6) { sMean[tid] = mean[tid]; sStd[tid] = stdv[tid]; }
    if (tid < 2) { sB[tid] = b31[tid]; sB[2 + tid] = b32[tid]; }
    __syncthreads();

    const int row = blockIdx.x * 64 + tid;
    if (row >= B) return;

    float x0[6];
    #pragma unroll
    for (int i = 0; i < 6; ++i)
        x0[i] = fmaf(x[(size_t)row * 8 + i], sStd[i], sMean[i]);

    const float px = x0[0], py = x0[1], theta = x0[2], v = x0[3];
    float st, ct;
    sincosf(theta, &st, &ct);

    const float p0  = g_headAcc[(size_t)row * 4 + 0] + sB[0];
    const float p1  = g_headAcc[(size_t)row * 4 + 1] + sB[1];
    const float pp1 = 4.0f / (1.0f + expf(-(g_headAcc[(size_t)row * 4 + 2] + sB[2])));
    const float pp2 = 4.0f / (1.0f + expf(-(g_headAcc[(size_t)row * 4 + 3] + sB[3])));

    const float twovv = 2.0f * v * v;
    const float psum  = pp1 + pp2;
    const float pprod = pp1 * pp2;

    float g1[9], g2[9], q[9];
    #pragma unroll
    for (int m = 0; m < 9; ++m) {
        float ox, oy, orad;
        if (m < 8) { ox = sObs[m * 3]; oy = sObs[m * 3 + 1]; orad = sObs[m * 3 + 2]; }
        else       { ox = x0[4];       oy = x0[5];           orad = 0.5f; }
        const float dx = px - ox, dy = py - oy;
        const float R  = orad + 0.6f;
        const float barrier = dx * dx + dy * dy - R * R;
        const float proj = dx * ct + dy * st;
        const float bdot = 2.0f * v * proj;
        g1[m] = 2.0f * v * (dx * st - dy * ct);
        g2[m] = -2.0f * proj;
        const float hm = twovv + psum * bdot + pprod * barrier;
        q[m] = fmaf(g1[m], p0, fmaf(g2[m], p1, hm));
    }

    float a = 0.f, bq = 0.f, c = 0.f;
    #pragma unroll
    for (int m = 0; m < 9; ++m) {
        a  = fmaf(g1[m], g1[m], a);
        bq = fmaf(g2[m], g2[m], bq);
        c  = fmaf(g1[m], g2[m], c);
    }
    const float L = sqrtf(a * a + 2.0f * c * c + bq * bq) + 1e-6f;
    const float alpha = 1.0f / L;

    float lam[9];
    #pragma unroll
    for (int m = 0; m < 9; ++m) lam[m] = 0.0f;

    for (int it = 0; it < 300; ++it) {
        float t1 = ((g1[0]*lam[0] + g1[1]*lam[1]) + (g1[2]*lam[2] + g1[3]*lam[3]))
                 + ((g1[4]*lam[4] + g1[5]*lam[5]) + (g1[6]*lam[6] + g1[7]*lam[7]))
                 + g1[8]*lam[8];
        float t2 = ((g2[0]*lam[0] + g2[1]*lam[1]) + (g2[2]*lam[2] + g2[3]*lam[3]))
                 + ((g2[4]*lam[4] + g2[5]*lam[5]) + (g2[6]*lam[6] + g2[7]*lam[7]))
                 + g2[8]*lam[8];
        #pragma unroll
        for (int m = 0; m < 9; ++m) {
            const float grad = fmaf(g1[m], t1, fmaf(g2[m], t2, q[m]));
            lam[m] = fmaxf(fmaf(-alpha, grad, lam[m]), 0.0f);
        }
    }

    float t1 = 0.f, t2 = 0.f;
    #pragma unroll
    for (int m = 0; m < 9; ++m) {
        t1 = fmaf(g1[m], lam[m], t1);
        t2 = fmaf(g2[m], lam[m], t2);
    }
    out[(size_t)row * 2 + 0] = -p0 - t1;
    out[(size_t)row * 2 + 1] = -p1 - t2;
}

// ---------------------------------------------------------------------------
extern "C" void kernel_launch(void* const* d_in, const int* in_sizes, int n_in,
                              void* d_out, int out_size)
{
    const float* x    = (const float*)d_in[0];
    const float* mean = (const float*)d_in[1];
    const float* stdv = (const float*)d_in[2];
    const float* W1   = (const float*)d_in[3];
    const float* b1   = (const float*)d_in[4];
    const float* W21  = (const float*)d_in[5];
    const float* b21  = (const float*)d_in[6];
    const float* W22  = (const float*)d_in[7];
    const float* b22  = (const float*)d_in[8];
    const float* W31  = (const float*)d_in[11];
    const float* b31  = (const float*)d_in[12];
    const float* W32  = (const float*)d_in[13];
    const float* b32  = (const float*)d_in[14];
    const float* obstacles = (const float*)d_in[17];
    float* out = (float*)d_out;

    int B = in_sizes[0] / 8;
    if (B > BMAX) B = BMAX;

    cudaFuncSetAttribute(gemm2_kernel,
                         cudaFuncAttributeMaxDynamicSharedMemorySize, SMEM_DYN);

    gemm1_kernel<<<(B + 31) / 32, 256>>>(x, W1, b1, B);
    wconv_kernel<<<dim3(16, 32, 2), dim3(32, 8)>>>(W21, W22);

    dim3 g2(8, (B + 127) / 128);
    gemm2_kernel<<<g2, 256, SMEM_DYN>>>(b21, b22, W31, W32);

    qp_kernel<<<(B + 63) / 64, 64>>>(x, mean, stdv, obstacles, b31, b32, out, B);
}

// round 6
// speedup vs baseline: 4.4848x; 1.4058x over previous
#include <cuda_runtime.h>
#include <cuda_fp16.h>
#include <math.h>
#include <stdint.h>

// ===========================================================================
// BarrierNet on GB300 (generic compute_103 PTX -> legacy HMMA, rt~16/SMSP):
//   gemm1 : h1 = relu(x@W1+b1) -> fp16 A
//   wconv : [W21|W22]^T -> fp16 B (single precision product; error budget
//           calibrated: A-only gave 1.53e-4, A+B ~2.5e-4 << 1e-3)
//   gemm2 : mma.sync fp16 single-product GEMM, 128x128 CTA tile, 2 CTA/SM,
//           head dots fused in epilogue (atomicAdd) -- C never materialized
//   qp    : per-row rank-2 dual PGA, eps early exit every 4 iters
// ===========================================================================

#define BMAX 8192

__device__ __align__(16) __half g_A[(size_t)BMAX * 1024];
__device__ __align__(16) __half g_B[1024 * 1024];   // [n][k]
__device__ float g_headAcc[(size_t)BMAX * 4];

// ---------------------------------------------------------------------------
__device__ __forceinline__ uint32_t smem_u32(const void* p) {
    uint32_t a;
    asm("{ .reg .u64 t; cvta.to.shared.u64 t, %1; cvt.u32.u64 %0, t; }" : "=r"(a) : "l"(p));
    return a;
}
__device__ __forceinline__ void cpasync16(uint32_t s, const void* g) {
    asm volatile("cp.async.cg.shared.global [%0], [%1], 16;" :: "r"(s), "l"(g));
}
#define CP_COMMIT() asm volatile("cp.async.commit_group;" ::: "memory")
#define CP_WAIT1()  asm volatile("cp.async.wait_group 1;" ::: "memory")

__device__ __forceinline__ void ldsm_x4(uint32_t* r, uint32_t addr) {
    asm volatile("ldmatrix.sync.aligned.m8n8.x4.shared.b16 {%0,%1,%2,%3}, [%4];"
                 : "=r"(r[0]), "=r"(r[1]), "=r"(r[2]), "=r"(r[3]) : "r"(addr));
}
__device__ __forceinline__ void mma_f16(float* d, const uint32_t* a, const uint32_t* b) {
    asm volatile(
        "mma.sync.aligned.m16n8k16.row.col.f32.f16.f16.f32 "
        "{%0,%1,%2,%3}, {%4,%5,%6,%7}, {%8,%9}, {%0,%1,%2,%3};"
        : "+f"(d[0]), "+f"(d[1]), "+f"(d[2]), "+f"(d[3])
        : "r"(a[0]), "r"(a[1]), "r"(a[2]), "r"(a[3]), "r"(b[0]), "r"(b[1]));
}

// ---------------------------------------------------------------------------
// Kernel 1: 32 rows per block, W1 resident in smem -> fp16 A
// ---------------------------------------------------------------------------
__global__ __launch_bounds__(256)
void gemm1_kernel(const float* __restrict__ x,
                  const float* __restrict__ W1,
                  const float* __restrict__ b1, int B)
{
    __shared__ float W1s[8 * 1024];
    __shared__ float xs[32][8];
    const int tid = threadIdx.x;
    const int r0  = blockIdx.x * 32;

    #pragma unroll
    for (int j = 0; j < 32; ++j)
        W1s[tid + j * 256] = W1[tid + j * 256];
    xs[tid >> 3][tid & 7] = x[(size_t)(r0 + (tid >> 3)) * 8 + (tid & 7)];
    if (tid < 128) g_headAcc[(size_t)r0 * 4 + tid] = 0.0f;
    __syncthreads();

    float w[4][8], bb[4];
    #pragma unroll
    for (int c = 0; c < 4; ++c) {
        const int col = tid + c * 256;
        bb[c] = b1[col];
        #pragma unroll
        for (int k = 0; k < 8; ++k) w[c][k] = W1s[k * 1024 + col];
    }

    for (int r = 0; r < 32; ++r) {
        float xr[8];
        #pragma unroll
        for (int k = 0; k < 8; ++k) xr[k] = xs[r][k];
        #pragma unroll
        for (int c = 0; c < 4; ++c) {
            float acc = bb[c];
            #pragma unroll
            for (int k = 0; k < 8; ++k) acc = fmaf(xr[k], w[c][k], acc);
            g_A[(size_t)(r0 + r) * 1024 + tid + c * 256] =
                __float2half(fmaxf(acc, 0.0f));
        }
    }
}

// ---------------------------------------------------------------------------
// Kernel 1b: transpose + fp16 convert of W21/W22 -> g_B[n][k]
// ---------------------------------------------------------------------------
__global__ void wconv_kernel(const float* __restrict__ W21,
                             const float* __restrict__ W22)
{
    __shared__ float tile[32][33];
    const float* W = blockIdx.z ? W22 : W21;
    const int n0 = blockIdx.x * 32;
    const int k0 = blockIdx.y * 32;
    const int tx = threadIdx.x, ty = threadIdx.y;
    #pragma unroll
    for (int i = ty; i < 32; i += 8)
        tile[i][tx] = W[(size_t)(k0 + i) * 512 + n0 + tx];
    __syncthreads();
    const int zb = blockIdx.z * 512;
    #pragma unroll
    for (int i = ty; i < 32; i += 8)
        g_B[(size_t)(zb + n0 + i) * 1024 + k0 + tx] = __float2half(tile[tx][i]);
}

// ---------------------------------------------------------------------------
// Kernel 2: fp16 single-product GEMM, 128(m) x 128(n) CTA tile, 2 CTA/SM.
// 8 warps = 2(m) x 4(n), warp tile 64x32. Per k16: 4mb x 4nb = 16 mma.
// ---------------------------------------------------------------------------
#define PITCHB   80u
#define OFF_A    0u
#define OFF_B    (128u * PITCHB)            // 10240
#define STAGE_BYTES (2u * 128u * PITCHB)    // 20480
#define SMEM_DYN (2u * STAGE_BYTES)         // 40960

__global__ __launch_bounds__(256, 2)
void gemm2_kernel(const float* __restrict__ b21, const float* __restrict__ b22,
                  const float* __restrict__ W31, const float* __restrict__ W32)
{
    extern __shared__ char smem[];
    __shared__ float sBias[128];
    __shared__ float sWh[256];

    const uint32_t sb = smem_u32(smem);
    const int tid  = threadIdx.x;
    const int lane = tid & 31;
    const int wid  = tid >> 5;
    const int wm   = wid & 1;           // 0..1
    const int wn   = wid >> 1;          // 0..3
    const int m0   = blockIdx.y * 128;
    const int n0   = blockIdx.x * 128;
    const int half = (n0 >= 512);
    const int nloc = n0 - half * 512;

    if (tid < 128) {
        const float* bp = half ? b22 : b21;
        const float* wp = half ? W32 : W31;
        sBias[tid]       = bp[nloc + tid];
        sWh[2 * tid]     = wp[(nloc + tid) * 2];
        sWh[2 * tid + 1] = wp[(nloc + tid) * 2 + 1];
    }

    const __half* __restrict__ srcA = g_A + (size_t)m0 * 1024;
    const __half* __restrict__ srcB = g_B + (size_t)n0 * 1024;

    const int lrow = tid >> 2;           // 0..63
    const int c8   = (tid & 3) * 8;
    const uint32_t cB = (uint32_t)(tid & 3) * 16u;

    const uint32_t aRC = (uint32_t)(wm * 64 + (lane & 15)) * PITCHB + (uint32_t)(lane >> 4) * 16u;
    const uint32_t bRC = (uint32_t)(wn * 32 + (lane & 7) + ((lane >> 4) << 3)) * PITCHB
                       + (uint32_t)((lane >> 3) & 1) * 16u;

    float acc[4][4][4];
    #pragma unroll
    for (int mb = 0; mb < 4; ++mb)
        #pragma unroll
        for (int nb = 0; nb < 4; ++nb)
            #pragma unroll
            for (int r = 0; r < 4; ++r) acc[mb][nb][r] = 0.0f;

    #define LOAD_STAGE(sbase, k0)                                                   \
    do {                                                                            \
        _Pragma("unroll")                                                           \
        for (int j = 0; j < 2; ++j) {                                               \
            const int r = lrow + j * 64;                                            \
            cpasync16((sbase) + OFF_A + (uint32_t)r * PITCHB + cB,                  \
                      srcA + (size_t)r * 1024 + (k0) + c8);                         \
            cpasync16((sbase) + OFF_B + (uint32_t)r * PITCHB + cB,                  \
                      srcB + (size_t)r * 1024 + (k0) + c8);                         \
        }                                                                           \
    } while (0)

    LOAD_STAGE(sb, 0);
    CP_COMMIT();

    for (int t = 0; t < 32; ++t) {
        if (t + 1 < 32) {
            const uint32_t s = sb + (uint32_t)((t + 1) & 1) * STAGE_BYTES;
            LOAD_STAGE(s, (t + 1) * 32);
        }
        CP_COMMIT();
        CP_WAIT1();
        __syncthreads();

        const uint32_t s = sb + (uint32_t)(t & 1) * STAGE_BYTES;
        #pragma unroll
        for (int ks = 0; ks < 2; ++ks) {
            const uint32_t kb = (uint32_t)ks * 32u;
            uint32_t bregs[4][2];
            #pragma unroll
            for (int nbp = 0; nbp < 2; ++nbp) {
                uint32_t r4[4];
                ldsm_x4(r4, s + OFF_B + bRC + (uint32_t)nbp * (16u * PITCHB) + kb);
                bregs[2 * nbp][0] = r4[0]; bregs[2 * nbp][1] = r4[1];
                bregs[2 * nbp + 1][0] = r4[2]; bregs[2 * nbp + 1][1] = r4[3];
            }
            #pragma unroll
            for (int mb = 0; mb < 4; ++mb) {
                uint32_t a4[4];
                ldsm_x4(a4, s + OFF_A + aRC + (uint32_t)mb * (16u * PITCHB) + kb);
                #pragma unroll
                for (int nb = 0; nb < 4; ++nb)
                    mma_f16(acc[mb][nb], a4, bregs[nb]);
            }
        }
        __syncthreads();
    }

    // epilogue: bias+relu, head dots, quad reduce, atomicAdd
    const int colBase = wn * 32;
    #pragma unroll
    for (int mb = 0; mb < 4; ++mb) {
        #pragma unroll
        for (int h = 0; h < 2; ++h) {
            float s0 = 0.f, s1 = 0.f;
            #pragma unroll
            for (int nb = 0; nb < 4; ++nb) {
                const int c = colBase + nb * 8 + 2 * (lane & 3);
                const float v0 = fmaxf(acc[mb][nb][h * 2 + 0] + sBias[c],     0.f);
                const float v1 = fmaxf(acc[mb][nb][h * 2 + 1] + sBias[c + 1], 0.f);
                s0 = fmaf(v0, sWh[2 * c],     fmaf(v1, sWh[2 * (c + 1)],     s0));
                s1 = fmaf(v0, sWh[2 * c + 1], fmaf(v1, sWh[2 * (c + 1) + 1], s1));
            }
            s0 += __shfl_xor_sync(0xffffffffu, s0, 1);
            s0 += __shfl_xor_sync(0xffffffffu, s0, 2);
            s1 += __shfl_xor_sync(0xffffffffu, s1, 1);
            s1 += __shfl_xor_sync(0xffffffffu, s1, 2);
            if ((lane & 3) == 0) {
                const int row = m0 + wm * 64 + mb * 16 + h * 8 + (lane >> 2);
                float* dst = g_headAcc + (size_t)row * 4 + half * 2;
                atomicAdd(dst,     s0);
                atomicAdd(dst + 1, s1);
            }
        }
    }
}

// ---------------------------------------------------------------------------
// Kernel 3: per-row QP (rank-2 dual PGA), eps early exit every 4 iters.
// Exit when per-iter |dLam|_inf <= 1e-6 * |lam|_inf across the whole warp:
// remaining reference iterations move lam by <= ~1e-6*scale (contraction),
// so outputs agree to ~1e-5 — far inside the 1e-3 gate.
// ---------------------------------------------------------------------------
__global__ __launch_bounds__(64)
void qp_kernel(const float* __restrict__ x,
               const float* __restrict__ mean,
               const float* __restrict__ stdv,
               const float* __restrict__ obstacles,
               const float* __restrict__ b31,
               const float* __restrict__ b32,
               float* __restrict__ out, int B)
{
    __shared__ float sObs[24];
    __shared__ float sMean[6], sStd[6], sB[4];
    const int tid = threadIdx.x;
    if (tid < 24) sObs[tid] = obstacles[tid];
    if (tid < 6) { sMean[tid] = mean[tid]; sStd[tid] = stdv[tid]; }
    if (tid < 2) { sB[tid] = b31[tid]; sB[2 + tid] = b32[tid]; }
    __syncthreads();

    const int rowReal = blockIdx.x * 64 + tid;
    const int row = rowReal < B ? rowReal : 0;   // keep warp intact for __all_sync

    float x0[6];
    #pragma unroll
    for (int i = 0; i < 6; ++i)
        x0[i] = fmaf(x[(size_t)row * 8 + i], sStd[i], sMean[i]);

    const float px = x0[0], py = x0[1], theta = x0[2], v = x0[3];
    float st, ct;
    sincosf(theta, &st, &ct);

    const float p0  = g_headAcc[(size_t)row * 4 + 0] + sB[0];
    const float p1  = g_headAcc[(size_t)row * 4 + 1] + sB[1];
    const float pp1 = 4.0f / (1.0f + expf(-(g_headAcc[(size_t)row * 4 + 2] + sB[2])));
    const float pp2 = 4.0f / (1.0f + expf(-(g_headAcc[(size_t)row * 4 + 3] + sB[3])));

    const float twovv = 2.0f * v * v;
    const float psum  = pp1 + pp2;
    const float pprod = pp1 * pp2;

    float g1[9], g2[9], q[9];
    #pragma unroll
    for (int m = 0; m < 9; ++m) {
        float ox, oy, orad;
        if (m < 8) { ox = sObs[m * 3]; oy = sObs[m * 3 + 1]; orad = sObs[m * 3 + 2]; }
        else       { ox = x0[4];       oy = x0[5];           orad = 0.5f; }
        const float dx = px - ox, dy = py - oy;
        const float R  = orad + 0.6f;
        const float barrier = dx * dx + dy * dy - R * R;
        const float proj = dx * ct + dy * st;
        const float bdot = 2.0f * v * proj;
        g1[m] = 2.0f * v * (dx * st - dy * ct);
        g2[m] = -2.0f * proj;
        const float hm = twovv + psum * bdot + pprod * barrier;
        q[m] = fmaf(g1[m], p0, fmaf(g2[m], p1, hm));
    }

    float a = 0.f, bq = 0.f, c = 0.f;
    #pragma unroll
    for (int m = 0; m < 9; ++m) {
        a  = fmaf(g1[m], g1[m], a);
        bq = fmaf(g2[m], g2[m], bq);
        c  = fmaf(g1[m], g2[m], c);
    }
    const float L = sqrtf(a * a + 2.0f * c * c + bq * bq) + 1e-6f;
    const float alpha = 1.0f / L;

    float lam[9];
    #pragma unroll
    for (int m = 0; m < 9; ++m) lam[m] = 0.0f;

    for (int blk = 0; blk < 75; ++blk) {
        // 3 plain iterations
        #pragma unroll
        for (int s = 0; s < 3; ++s) {
            float t1 = ((g1[0]*lam[0] + g1[1]*lam[1]) + (g1[2]*lam[2] + g1[3]*lam[3]))
                     + ((g1[4]*lam[4] + g1[5]*lam[5]) + (g1[6]*lam[6] + g1[7]*lam[7]))
                     + g1[8]*lam[8];
            float t2 = ((g2[0]*lam[0] + g2[1]*lam[1]) + (g2[2]*lam[2] + g2[3]*lam[3]))
                     + ((g2[4]*lam[4] + g2[5]*lam[5]) + (g2[6]*lam[6] + g2[7]*lam[7]))
                     + g2[8]*lam[8];
            #pragma unroll
            for (int m = 0; m < 9; ++m) {
                const float grad = fmaf(g1[m], t1, fmaf(g2[m], t2, q[m]));
                lam[m] = fmaxf(fmaf(-alpha, grad, lam[m]), 0.0f);
            }
        }
        // 4th iteration with convergence measurement
        {
            float t1 = ((g1[0]*lam[0] + g1[1]*lam[1]) + (g1[2]*lam[2] + g1[3]*lam[3]))
                     + ((g1[4]*lam[4] + g1[5]*lam[5]) + (g1[6]*lam[6] + g1[7]*lam[7]))
                     + g1[8]*lam[8];
            float t2 = ((g2[0]*lam[0] + g2[1]*lam[1]) + (g2[2]*lam[2] + g2[3]*lam[3]))
                     + ((g2[4]*lam[4] + g2[5]*lam[5]) + (g2[6]*lam[6] + g2[7]*lam[7]))
                     + g2[8]*lam[8];
            float chmax = 0.f, lmax = 0.f;
            #pragma unroll
            for (int m = 0; m < 9; ++m) {
                const float grad = fmaf(g1[m], t1, fmaf(g2[m], t2, q[m]));
                const float nl = fmaxf(fmaf(-alpha, grad, lam[m]), 0.0f);
                chmax = fmaxf(chmax, fabsf(nl - lam[m]));
                lmax  = fmaxf(lmax, nl);
                lam[m] = nl;
            }
            if (__all_sync(0xffffffffu, chmax <= 1e-6f * lmax)) break;
        }
    }

    float t1 = 0.f, t2 = 0.f;
    #pragma unroll
    for (int m = 0; m < 9; ++m) {
        t1 = fmaf(g1[m], lam[m], t1);
        t2 = fmaf(g2[m], lam[m], t2);
    }
    if (rowReal < B) {
        out[(size_t)rowReal * 2 + 0] = -p0 - t1;
        out[(size_t)rowReal * 2 + 1] = -p1 - t2;
    }
}

// ---------------------------------------------------------------------------
extern "C" void kernel_launch(void* const* d_in, const int* in_sizes, int n_in,
                              void* d_out, int out_size)
{
    const float* x    = (const float*)d_in[0];
    const float* mean = (const float*)d_in[1];
    const float* stdv = (const float*)d_in[2];
    const float* W1   = (const float*)d_in[3];
    const float* b1   = (const float*)d_in[4];
    const float* W21  = (const float*)d_in[5];
    const float* b21  = (const float*)d_in[6];
    const float* W22  = (const float*)d_in[7];
    const float* b22  = (const float*)d_in[8];
    const float* W31  = (const float*)d_in[11];
    const float* b31  = (const float*)d_in[12];
    const float* W32  = (const float*)d_in[13];
    const float* b32  = (const float*)d_in[14];
    const float* obstacles = (const float*)d_in[17];
    float* out = (float*)d_out;

    int B = in_sizes[0] / 8;
    if (B > BMAX) B = BMAX;

    cudaFuncSetAttribute(gemm2_kernel,
                         cudaFuncAttributeMaxDynamicSharedMemorySize, SMEM_DYN);

    gemm1_kernel<<<(B + 31) / 32, 256>>>(x, W1, b1, B);
    wconv_kernel<<<dim3(16, 32, 2), dim3(32, 8)>>>(W21, W22);

    dim3 g2(8, (B + 127) / 128);
    gemm2_kernel<<<g2, 256, SMEM_DYN>>>(b21, b22, W31, W32);

    qp_kernel<<<(B + 63) / 64, 64>>>(x, mean, stdv, obstacles, b31, b32, out, B);
}

// round 7
// speedup vs baseline: 5.2278x; 1.1657x over previous
#include <cuda_runtime.h>
#include <cuda_fp16.h>
#include <math.h>
#include <stdint.h>

// ===========================================================================
// BarrierNet on GB300 (generic compute_103 PTX -> legacy HMMA, rt~16/SMSP):
//   prep  : fused { h1=relu(x@W1+b1)->fp16 A ; [W21|W22]^T->fp16 B ; zero acc }
//   gemm2 : mma.sync fp16 GEMM, 128x128 CTA tile, 2 CTA/SM, 3-stage cp.async
//           (1 sync/stage), head dots fused in epilogue (atomicAdd)
//   qp    : rank-2 dual PGA, 2 lanes per row (shfl-paired reductions), 300 it
// ===========================================================================

#define BMAX 8192

__device__ __align__(16) __half g_A[(size_t)BMAX * 1024];
__device__ __align__(16) __half g_B[1024 * 1024];   // [n][k]
__device__ float g_headAcc[(size_t)BMAX * 4];

// ---------------------------------------------------------------------------
__device__ __forceinline__ uint32_t smem_u32(const void* p) {
    uint32_t a;
    asm("{ .reg .u64 t; cvta.to.shared.u64 t, %1; cvt.u32.u64 %0, t; }" : "=r"(a) : "l"(p));
    return a;
}
__device__ __forceinline__ void cpasync16(uint32_t s, const void* g) {
    asm volatile("cp.async.cg.shared.global [%0], [%1], 16;" :: "r"(s), "l"(g));
}
#define CP_COMMIT() asm volatile("cp.async.commit_group;" ::: "memory")
#define CP_WAIT1()  asm volatile("cp.async.wait_group 1;" ::: "memory")

__device__ __forceinline__ void ldsm_x4(uint32_t* r, uint32_t addr) {
    asm volatile("ldmatrix.sync.aligned.m8n8.x4.shared.b16 {%0,%1,%2,%3}, [%4];"
                 : "=r"(r[0]), "=r"(r[1]), "=r"(r[2]), "=r"(r[3]) : "r"(addr));
}
__device__ __forceinline__ void mma_f16(float* d, const uint32_t* a, const uint32_t* b) {
    asm volatile(
        "mma.sync.aligned.m16n8k16.row.col.f32.f16.f16.f32 "
        "{%0,%1,%2,%3}, {%4,%5,%6,%7}, {%8,%9}, {%0,%1,%2,%3};"
        : "+f"(d[0]), "+f"(d[1]), "+f"(d[2]), "+f"(d[3])
        : "r"(a[0]), "r"(a[1]), "r"(a[2]), "r"(a[3]), "r"(b[0]), "r"(b[1]));
}

// ---------------------------------------------------------------------------
// Kernel 1 (fused prep): blocks [0, nb1) do gemm1 (32 rows each, W1 in smem);
// blocks [nb1, nb1+1024) do wconv transpose+fp16.
// ---------------------------------------------------------------------------
__global__ __launch_bounds__(256)
void prep_kernel(const float* __restrict__ x,
                 const float* __restrict__ W1,
                 const float* __restrict__ b1,
                 const float* __restrict__ W21,
                 const float* __restrict__ W22,
                 int B, int nb1)
{
    __shared__ float sh[8 * 1024 + 256];
    const int tid = threadIdx.x;

    if ((int)blockIdx.x < nb1) {
        // ---- gemm1: h1 = relu(x@W1+b1) -> fp16 A ----
        float* W1s = sh;
        float* xs  = sh + 8192;     // [32][8]
        const int r0 = blockIdx.x * 32;

        #pragma unroll
        for (int j = 0; j < 32; ++j)
            W1s[tid + j * 256] = W1[tid + j * 256];
        xs[tid] = x[(size_t)r0 * 8 + tid];
        if (tid < 128) g_headAcc[(size_t)r0 * 4 + tid] = 0.0f;
        __syncthreads();

        float w[4][8], bb[4];
        #pragma unroll
        for (int c = 0; c < 4; ++c) {
            const int col = tid + c * 256;
            bb[c] = b1[col];
            #pragma unroll
            for (int k = 0; k < 8; ++k) w[c][k] = W1s[k * 1024 + col];
        }
        for (int r = 0; r < 32; ++r) {
            float xr[8];
            #pragma unroll
            for (int k = 0; k < 8; ++k) xr[k] = xs[r * 8 + k];
            #pragma unroll
            for (int c = 0; c < 4; ++c) {
                float acc = bb[c];
                #pragma unroll
                for (int k = 0; k < 8; ++k) acc = fmaf(xr[k], w[c][k], acc);
                g_A[(size_t)(r0 + r) * 1024 + tid + c * 256] =
                    __float2half(fmaxf(acc, 0.0f));
            }
        }
    } else {
        // ---- wconv: [W21|W22]^T -> g_B[n][k] fp16 ----
        const int wc = blockIdx.x - nb1;          // 0..1023
        const int z  = wc >> 9;                   // 0: W21, 1: W22
        const int r  = wc & 511;
        const int n0 = (r & 15) * 32;
        const int k0 = (r >> 4) * 32;
        const int tx = tid & 31, ty = tid >> 5;   // (32, 8)
        float (*tile)[33] = (float (*)[33])sh;
        const float* W = z ? W22 : W21;

        #pragma unroll
        for (int i = ty; i < 32; i += 8)
            tile[i][tx] = W[(size_t)(k0 + i) * 512 + n0 + tx];
        __syncthreads();
        const int zb = z * 512;
        #pragma unroll
        for (int i = ty; i < 32; i += 8)
            g_B[(size_t)(zb + n0 + i) * 1024 + k0 + tx] = __float2half(tile[tx][i]);
    }
}

// ---------------------------------------------------------------------------
// Kernel 2: fp16 GEMM, 128(m) x 128(n) CTA tile, 2 CTA/SM, 3-stage pipeline.
// 8 warps = 2(m) x 4(n), warp tile 64x32. One __syncthreads per k32 stage.
// ---------------------------------------------------------------------------
#define PITCHB   80u
#define OFF_A    0u
#define OFF_B    (128u * PITCHB)            // 10240
#define STAGE_BYTES (2u * 128u * PITCHB)    // 20480
#define SMEM_DYN (3u * STAGE_BYTES)         // 61440

__global__ __launch_bounds__(256, 2)
void gemm2_kernel(const float* __restrict__ b21, const float* __restrict__ b22,
                  const float* __restrict__ W31, const float* __restrict__ W32)
{
    extern __shared__ char smem[];
    __shared__ float sBias[128];
    __shared__ float sWh[256];

    const uint32_t sb = smem_u32(smem);
    const int tid  = threadIdx.x;
    const int lane = tid & 31;
    const int wid  = tid >> 5;
    const int wm   = wid & 1;
    const int wn   = wid >> 1;
    const int m0   = blockIdx.y * 128;
    const int n0   = blockIdx.x * 128;
    const int half = (n0 >= 512);
    const int nloc = n0 - half * 512;

    if (tid < 128) {
        const float* bp = half ? b22 : b21;
        const float* wp = half ? W32 : W31;
        sBias[tid]       = bp[nloc + tid];
        sWh[2 * tid]     = wp[(nloc + tid) * 2];
        sWh[2 * tid + 1] = wp[(nloc + tid) * 2 + 1];
    }

    const __half* __restrict__ srcA = g_A + (size_t)m0 * 1024;
    const __half* __restrict__ srcB = g_B + (size_t)n0 * 1024;

    const int lrow = tid >> 2;
    const int c8   = (tid & 3) * 8;
    const uint32_t cB = (uint32_t)(tid & 3) * 16u;

    const uint32_t aRC = (uint32_t)(wm * 64 + (lane & 15)) * PITCHB + (uint32_t)(lane >> 4) * 16u;
    const uint32_t bRC = (uint32_t)(wn * 32 + (lane & 7) + ((lane >> 4) << 3)) * PITCHB
                       + (uint32_t)((lane >> 3) & 1) * 16u;

    float acc[4][4][4];
    #pragma unroll
    for (int mb = 0; mb < 4; ++mb)
        #pragma unroll
        for (int nb = 0; nb < 4; ++nb)
            #pragma unroll
            for (int r = 0; r < 4; ++r) acc[mb][nb][r] = 0.0f;

    #define LOAD_STAGE(sbase, k0)                                                   \
    do {                                                                            \
        _Pragma("unroll")                                                           \
        for (int j = 0; j < 2; ++j) {                                               \
            const int r = lrow + j * 64;                                            \
            cpasync16((sbase) + OFF_A + (uint32_t)r * PITCHB + cB,                  \
                      srcA + (size_t)r * 1024 + (k0) + c8);                         \
            cpasync16((sbase) + OFF_B + (uint32_t)r * PITCHB + cB,                  \
                      srcB + (size_t)r * 1024 + (k0) + c8);                         \
        }                                                                           \
    } while (0)

    LOAD_STAGE(sb, 0);
    CP_COMMIT();
    LOAD_STAGE(sb + STAGE_BYTES, 32);
    CP_COMMIT();

    int cur = 0, nxt2 = 2;    // (t % 3), ((t+2) % 3)
    for (int t = 0; t < 32; ++t) {
        CP_WAIT1();            // stage t resident (<=1 group pending)
        __syncthreads();       // everyone done with stage t-1's buffer reuse

        const uint32_t s = sb + (uint32_t)cur * STAGE_BYTES;
        #pragma unroll
        for (int ks = 0; ks < 2; ++ks) {
            const uint32_t kb = (uint32_t)ks * 32u;
            uint32_t bregs[4][2];
            #pragma unroll
            for (int nbp = 0; nbp < 2; ++nbp) {
                uint32_t r4[4];
                ldsm_x4(r4, s + OFF_B + bRC + (uint32_t)nbp * (16u * PITCHB) + kb);
                bregs[2 * nbp][0] = r4[0]; bregs[2 * nbp][1] = r4[1];
                bregs[2 * nbp + 1][0] = r4[2]; bregs[2 * nbp + 1][1] = r4[3];
            }
            #pragma unroll
            for (int mb = 0; mb < 4; ++mb) {
                uint32_t a4[4];
                ldsm_x4(a4, s + OFF_A + aRC + (uint32_t)mb * (16u * PITCHB) + kb);
                #pragma unroll
                for (int nb = 0; nb < 4; ++nb)
                    mma_f16(acc[mb][nb], a4, bregs[nb]);
            }
        }

        if (t + 2 < 32)
            LOAD_STAGE(sb + (uint32_t)nxt2 * STAGE_BYTES, (t + 2) * 32);
        CP_COMMIT();
        cur  = (cur  == 2) ? 0 : cur  + 1;
        nxt2 = (nxt2 == 2) ? 0 : nxt2 + 1;
    }

    // epilogue: bias+relu, head dots, quad reduce, atomicAdd
    const int colBase = wn * 32;
    #pragma unroll
    for (int mb = 0; mb < 4; ++mb) {
        #pragma unroll
        for (int h = 0; h < 2; ++h) {
            float s0 = 0.f, s1 = 0.f;
            #pragma unroll
            for (int nb = 0; nb < 4; ++nb) {
                const int c = colBase + nb * 8 + 2 * (lane & 3);
                const float v0 = fmaxf(acc[mb][nb][h * 2 + 0] + sBias[c],     0.f);
                const float v1 = fmaxf(acc[mb][nb][h * 2 + 1] + sBias[c + 1], 0.f);
                s0 = fmaf(v0, sWh[2 * c],     fmaf(v1, sWh[2 * (c + 1)],     s0));
                s1 = fmaf(v0, sWh[2 * c + 1], fmaf(v1, sWh[2 * (c + 1) + 1], s1));
            }
            s0 += __shfl_xor_sync(0xffffffffu, s0, 1);
            s0 += __shfl_xor_sync(0xffffffffu, s0, 2);
            s1 += __shfl_xor_sync(0xffffffffu, s1, 1);
            s1 += __shfl_xor_sync(0xffffffffu, s1, 2);
            if ((lane & 3) == 0) {
                const int row = m0 + wm * 64 + mb * 16 + h * 8 + (lane >> 2);
                float* dst = g_headAcc + (size_t)row * 4 + half * 2;
                atomicAdd(dst,     s0);
                atomicAdd(dst + 1, s1);
            }
        }
    }
}

// ---------------------------------------------------------------------------
// Kernel 3: QP, 2 lanes per row. Even lane owns m=0..4, odd lane m=5..8 (+dummy).
// t1/t2 = partial dot + shfl_xor(1). Fixed 300 iterations.
// ---------------------------------------------------------------------------
__global__ __launch_bounds__(128)
void qp_kernel(const float* __restrict__ x,
               const float* __restrict__ mean,
               const float* __restrict__ stdv,
               const float* __restrict__ obstacles,
               const float* __restrict__ b31,
               const float* __restrict__ b32,
               float* __restrict__ out, int B)
{
    __shared__ float sObs[24];
    __shared__ float sMean[6], sStd[6], sB[4];
    const int tid = threadIdx.x;
    if (tid < 24) sObs[tid] = obstacles[tid];
    if (tid < 6) { sMean[tid] = mean[tid]; sStd[tid] = stdv[tid]; }
    if (tid < 2) { sB[tid] = b31[tid]; sB[2 + tid] = b32[tid]; }
    __syncthreads();

    const int gt   = blockIdx.x * 128 + tid;
    const int rowR = gt >> 1;                    // row
    const int par  = gt & 1;                     // 0: m 0..4, 1: m 5..8
    const int row  = rowR < B ? rowR : 0;

    float x0[6];
    #pragma unroll
    for (int i = 0; i < 6; ++i)
        x0[i] = fmaf(x[(size_t)row * 8 + i], sStd[i], sMean[i]);

    const float px = x0[0], py = x0[1], theta = x0[2], v = x0[3];
    float st, ct;
    sincosf(theta, &st, &ct);

    const float p0  = g_headAcc[(size_t)row * 4 + 0] + sB[0];
    const float p1  = g_headAcc[(size_t)row * 4 + 1] + sB[1];
    const float pp1 = 4.0f / (1.0f + expf(-(g_headAcc[(size_t)row * 4 + 2] + sB[2])));
    const float pp2 = 4.0f / (1.0f + expf(-(g_headAcc[(size_t)row * 4 + 3] + sB[3])));

    const float twovv = 2.0f * v * v;
    const float psum  = pp1 + pp2;
    const float pprod = pp1 * pp2;

    // This lane's 5 constraint slots (odd lane slot 4 = dummy zeros)
    float g1[5], g2[5], q[5];
    #pragma unroll
    for (int i = 0; i < 5; ++i) {
        const int m = par * 5 + i;
        if (m < 9) {
            float ox, oy, orad;
            if (m < 8) { ox = sObs[m * 3]; oy = sObs[m * 3 + 1]; orad = sObs[m * 3 + 2]; }
            else       { ox = x0[4];       oy = x0[5];           orad = 0.5f; }
            const float dx = px - ox, dy = py - oy;
            const float R  = orad + 0.6f;
            const float barrier = dx * dx + dy * dy - R * R;
            const float proj = dx * ct + dy * st;
            const float bdot = 2.0f * v * proj;
            g1[i] = 2.0f * v * (dx * st - dy * ct);
            g2[i] = -2.0f * proj;
            const float hm = twovv + psum * bdot + pprod * barrier;
            q[i] = fmaf(g1[i], p0, fmaf(g2[i], p1, hm));
        } else {
            g1[i] = 0.f; g2[i] = 0.f; q[i] = 0.f;
        }
    }

    // Lipschitz constant from full sums (pairwise shfl)
    float a = 0.f, bq = 0.f, c = 0.f;
    #pragma unroll
    for (int i = 0; i < 5; ++i) {
        a  = fmaf(g1[i], g1[i], a);
        bq = fmaf(g2[i], g2[i], bq);
        c  = fmaf(g1[i], g2[i], c);
    }
    a  += __shfl_xor_sync(0xffffffffu, a,  1);
    bq += __shfl_xor_sync(0xffffffffu, bq, 1);
    c  += __shfl_xor_sync(0xffffffffu, c,  1);
    const float L = sqrtf(a * a + 2.0f * c * c + bq * bq) + 1e-6f;
    const float alpha = 1.0f / L;

    float lam[5];
    #pragma unroll
    for (int i = 0; i < 5; ++i) lam[i] = 0.0f;

    for (int it = 0; it < 300; ++it) {
        float t1p = ((g1[0] * lam[0] + g1[1] * lam[1]) +
                     (g1[2] * lam[2] + g1[3] * lam[3])) + g1[4] * lam[4];
        float t2p = ((g2[0] * lam[0] + g2[1] * lam[1]) +
                     (g2[2] * lam[2] + g2[3] * lam[3])) + g2[4] * lam[4];
        const float t1 = t1p + __shfl_xor_sync(0xffffffffu, t1p, 1);
        const float t2 = t2p + __shfl_xor_sync(0xffffffffu, t2p, 1);
        #pragma unroll
        for (int i = 0; i < 5; ++i) {
            const float grad = fmaf(g1[i], t1, fmaf(g2[i], t2, q[i]));
            lam[i] = fmaxf(fmaf(-alpha, grad, lam[i]), 0.0f);
        }
    }

    float t1p = 0.f, t2p = 0.f;
    #pragma unroll
    for (int i = 0; i < 5; ++i) {
        t1p = fmaf(g1[i], lam[i], t1p);
        t2p = fmaf(g2[i], lam[i], t2p);
    }
    const float t1 = t1p + __shfl_xor_sync(0xffffffffu, t1p, 1);
    const float t2 = t2p + __shfl_xor_sync(0xffffffffu, t2p, 1);
    if (par == 0 && rowR < B) {
        out[(size_t)rowR * 2 + 0] = -p0 - t1;
        out[(size_t)rowR * 2 + 1] = -p1 - t2;
    }
}

// ---------------------------------------------------------------------------
extern "C" void kernel_launch(void* const* d_in, const int* in_sizes, int n_in,
                              void* d_out, int out_size)
{
    const float* x    = (const float*)d_in[0];
    const float* mean = (const float*)d_in[1];
    const float* stdv = (const float*)d_in[2];
    const float* W1   = (const float*)d_in[3];
    const float* b1   = (const float*)d_in[4];
    const float* W21  = (const float*)d_in[5];
    const float* b21  = (const float*)d_in[6];
    const float* W22  = (const float*)d_in[7];
    const float* b22  = (const float*)d_in[8];
    const float* W31  = (const float*)d_in[11];
    const float* b31  = (const float*)d_in[12];
    const float* W32  = (const float*)d_in[13];
    const float* b32  = (const float*)d_in[14];
    const float* obstacles = (const float*)d_in[17];
    float* out = (float*)d_out;

    int B = in_sizes[0] / 8;
    if (B > BMAX) B = BMAX;

    cudaFuncSetAttribute(gemm2_kernel,
                         cudaFuncAttributeMaxDynamicSharedMemorySize, SMEM_DYN);

    const int nb1 = (B + 31) / 32;
    prep_kernel<<<nb1 + 1024, 256>>>(x, W1, b1, W21, W22, B, nb1);

    dim3 g2(8, (B + 127) / 128);
    gemm2_kernel<<<g2, 256, SMEM_DYN>>>(b21, b22, W31, W32);

    qp_kernel<<<(2 * B + 127) / 128, 128>>>(x, mean, stdv, obstacles, b31, b32, out, B);
}